// round 6
// baseline (speedup 1.0000x reference)
#include <cuda_runtime.h>
#include <cuda_bf16.h>
#include <math.h>
#include <stdint.h>

#define B 32
#define T 2048
#define E 512
#define D 1024
#define H 128

#define TS 32      // t-splits in context pass
#define KC 32      // k-chunk (e) per stage in k_erg

// ---- scratch ----
__device__ float g_dec[B * H];
__device__ float g_erg[B * T];
__device__ float g_ctx_part[TS][B][E];
__device__ __nv_bfloat16 g_wbf_hi[H * E];   // W_enc^T hi: [h][e]
__device__ __nv_bfloat16 g_wbf_lo[H * E];   // residual

// ===========================================================================
// helpers
// ===========================================================================
__device__ __forceinline__ uint32_t smem_u32(const void* p) {
    uint32_t a;
    asm("{ .reg .u64 t; cvta.to.shared.u64 t, %1; cvt.u32.u64 %0, t; }"
        : "=r"(a) : "l"(p));
    return a;
}
__device__ __forceinline__ void cp_async16(uint32_t dst, const void* src) {
    asm volatile("cp.async.ca.shared.global [%0], [%1], 16;"
                 :: "r"(dst), "l"(src) : "memory");
}
__device__ __forceinline__ void cp_commit() {
    asm volatile("cp.async.commit_group;" ::: "memory");
}
__device__ __forceinline__ void cp_wait1() {
    asm volatile("cp.async.wait_group 1;" ::: "memory");
}
__device__ __forceinline__ void cp_wait0() {
    asm volatile("cp.async.wait_group 0;" ::: "memory");
}
__device__ __forceinline__ void split2(float x, float y, uint32_t& hi, uint32_t& lo) {
    asm("cvt.rn.bf16x2.f32 %0, %1, %2;" : "=r"(hi) : "f"(y), "f"(x));
    float hx = __uint_as_float(hi << 16);
    float hy = __uint_as_float(hi & 0xFFFF0000u);
    float lx = x - hx, ly = y - hy;
    asm("cvt.rn.bf16x2.f32 %0, %1, %2;" : "=r"(lo) : "f"(ly), "f"(lx));
}
__device__ __forceinline__ void mma_bf16(float* c, const uint32_t* a,
                                         uint32_t b0, uint32_t b1) {
    asm volatile(
        "mma.sync.aligned.m16n8k16.row.col.f32.bf16.bf16.f32 "
        "{%0,%1,%2,%3}, {%4,%5,%6,%7}, {%8,%9}, {%0,%1,%2,%3};"
        : "+f"(c[0]), "+f"(c[1]), "+f"(c[2]), "+f"(c[3])
        : "r"(a[0]), "r"(a[1]), "r"(a[2]), "r"(a[3]), "r"(b0), "r"(b1));
}
// XOR swizzle on 4-u32 blocks: row stride 16 u32.
// Element address map: row*16 + (col ^ (((row>>1)&3)<<2)).
// 16B blocks must each be stored at the swizzled address of their OWN block start.
__device__ __forceinline__ int swz(int row, int col) {
    return row * 16 + (col ^ (((row >> 1) & 3) << 2));
}

// ===========================================================================
// k_wprep: W_enc [E][H] -> bf16 hi/lo transposed [H][E]
// ===========================================================================
__global__ void k_wprep(const float* __restrict__ W) {
    __shared__ float tile[32][33];
    const int e0 = blockIdx.x * 32, h0 = blockIdx.y * 32;
    const int tx = threadIdx.x, ty = threadIdx.y;
    tile[ty][tx] = W[(size_t)(e0 + ty) * H + h0 + tx];
    __syncthreads();
    float v = tile[tx][ty];
    __nv_bfloat16 hb = __float2bfloat16_rn(v);
    float lo = v - __bfloat162float(hb);
    g_wbf_hi[(size_t)(h0 + ty) * E + e0 + tx] = hb;
    g_wbf_lo[(size_t)(h0 + ty) * E + e0 + tx] = __float2bfloat16_rn(lo);
}

// ===========================================================================
// k_dec
// ===========================================================================
__global__ __launch_bounds__(1024)
void k_dec(const float* __restrict__ ds, const float* __restrict__ Wdec,
           const float* __restrict__ benc) {
    __shared__ float s[8][128];
    const int b = blockIdx.x;
    const int h = threadIdx.x, ty = threadIdx.y;
    float acc = 0.f;
    const float* dsr = ds + b * D + ty * 128;
    const float* wp = Wdec + (size_t)(ty * 128) * H + h;
#pragma unroll 8
    for (int d = 0; d < 128; d++)
        acc = fmaf(dsr[d], wp[(size_t)d * H], acc);
    s[ty][h] = acc;
    __syncthreads();
    if (ty == 0) {
        float t = benc[h];
#pragma unroll
        for (int k = 0; k < 8; k++) t += s[k][h];
        g_dec[b * H + h] = t;
    }
}

// ===========================================================================
// k_erg: pipelined HMMA bf16 3-split GEMM + fused epilogue
// grid 512, block 256 (8 warps; warp = 32t x 64h)
// Static smem = 48KB: A_hi, A_lo (single-buffered) + W_hi[2], W_lo[2]
// ===========================================================================
#define TILEU (128 * 16)          // 2048 u32 per packed tile
#define O_AHI 0
#define O_ALO TILEU
#define O_WHI(buf) (2 * TILEU + (buf) * TILEU)
#define O_WLO(buf) (4 * TILEU + (buf) * TILEU)

__global__ __launch_bounds__(256, 2)
void k_erg(const float* __restrict__ enc, const float* __restrict__ ww,
           const float* __restrict__ wbp) {
    __shared__ uint32_t sm[6 * TILEU];     // 49152 bytes

    const int tid = threadIdx.x;
    const int w = tid >> 5, lane = tid & 31;
    const int g = lane >> 2, tig = lane & 3;
    const int b = blockIdx.x >> 4;
    const int t0 = (blockIdx.x & 15) * 128;
    const int mrow0 = (w & 3) * 32;
    const int ncol0 = (w >> 2) * 64;

    const uint32_t sb = smem_u32(sm);
    // W cp.async: 512 (row,seg) pairs over 256 threads x2
    const int wrow0 = tid >> 2;
    const int wrow1 = (tid + 256) >> 2;
    const int wseg = tid & 3;
    const uint32_t wdst0 = (uint32_t)swz(wrow0, wseg * 4) * 4;
    const uint32_t wdst1 = (uint32_t)swz(wrow1, wseg * 4) * 4;

    const int arow = tid >> 1, ahalf = tid & 1;
    const float* aptr = enc + (size_t)(b * T + t0 + arow) * E + ahalf * 16;
    // each 16B (4-u32) block placed at its own swizzled block address
    const uint32_t adst0 = (uint32_t)swz(arow, ahalf * 8);
    const uint32_t adst1 = (uint32_t)swz(arow, ahalf * 8 + 4);

    float acc[2][8][4];
#pragma unroll
    for (int mt = 0; mt < 2; mt++)
#pragma unroll
        for (int nt = 0; nt < 8; nt++)
#pragma unroll
            for (int j = 0; j < 4; j++) acc[mt][nt][j] = 0.f;

    // ---- prologue: W chunk 0 -> buf0; enc chunk 0 -> regs ----
    {
        const uint32_t whi = sb + O_WHI(0) * 4, wlo = sb + O_WLO(0) * 4;
        cp_async16(whi + wdst0, g_wbf_hi + (size_t)wrow0 * E + wseg * 8);
        cp_async16(whi + wdst1, g_wbf_hi + (size_t)wrow1 * E + wseg * 8);
        cp_async16(wlo + wdst0, g_wbf_lo + (size_t)wrow0 * E + wseg * 8);
        cp_async16(wlo + wdst1, g_wbf_lo + (size_t)wrow1 * E + wseg * 8);
        cp_commit();
    }
    float4 pre0 = *(const float4*)(aptr);
    float4 pre1 = *(const float4*)(aptr + 4);
    float4 pre2 = *(const float4*)(aptr + 8);
    float4 pre3 = *(const float4*)(aptr + 12);

#pragma unroll 1
    for (int c = 0; c < 16; c++) {
        const int buf = c & 1;
        float4 f0 = pre0, f1 = pre1, f2 = pre2, f3 = pre3;
        if (c < 15) {   // prefetch enc chunk c+1
            const float* ap = aptr + (c + 1) * KC;
            pre0 = *(const float4*)(ap);
            pre1 = *(const float4*)(ap + 4);
            pre2 = *(const float4*)(ap + 8);
            pre3 = *(const float4*)(ap + 12);
        }

        __syncthreads();   // MMA(c-1) done: safe to overwrite A and W buf^1

        // issue W chunk c+1 into buf^1 (in flight across MMA(c))
        if (c < 15) {
            const int nb = buf ^ 1;
            const uint32_t whi = sb + O_WHI(nb) * 4, wlo = sb + O_WLO(nb) * 4;
            const size_t go = (size_t)(c + 1) * KC;
            cp_async16(whi + wdst0, g_wbf_hi + (size_t)wrow0 * E + go + wseg * 8);
            cp_async16(whi + wdst1, g_wbf_hi + (size_t)wrow1 * E + go + wseg * 8);
            cp_async16(wlo + wdst0, g_wbf_lo + (size_t)wrow0 * E + go + wseg * 8);
            cp_async16(wlo + wdst1, g_wbf_lo + (size_t)wrow1 * E + go + wseg * 8);
            cp_commit();
        }

        // convert A(c) -> smem
        uint32_t h0, h1, h2, h3, h4, h5, h6, h7;
        uint32_t l0, l1, l2, l3, l4, l5, l6, l7;
        split2(f0.x, f0.y, h0, l0); split2(f0.z, f0.w, h1, l1);
        split2(f1.x, f1.y, h2, l2); split2(f1.z, f1.w, h3, l3);
        split2(f2.x, f2.y, h4, l4); split2(f2.z, f2.w, h5, l5);
        split2(f3.x, f3.y, h6, l6); split2(f3.z, f3.w, h7, l7);
        *(uint4*)&sm[O_AHI + adst0] = make_uint4(h0, h1, h2, h3);
        *(uint4*)&sm[O_AHI + adst1] = make_uint4(h4, h5, h6, h7);
        *(uint4*)&sm[O_ALO + adst0] = make_uint4(l0, l1, l2, l3);
        *(uint4*)&sm[O_ALO + adst1] = make_uint4(l4, l5, l6, l7);

        // W(c) complete; at c==15 nothing was committed after it -> wait all
        if (c < 15) cp_wait1(); else cp_wait0();
        __syncthreads();   // A(c) + W(c) visible to all warps

        // MMA on chunk c
        const uint32_t* Wh = sm + O_WHI(buf);
        const uint32_t* Wl = sm + O_WLO(buf);
#pragma unroll
        for (int ks = 0; ks < 2; ks++) {
            uint32_t ah[2][4], al[2][4];
#pragma unroll
            for (int mt = 0; mt < 2; mt++) {
                const int r = mrow0 + mt * 16 + g;
                const int i0 = swz(r, ks * 8 + tig);
                const int i1 = swz(r + 8, ks * 8 + tig);
                const int i2 = swz(r, ks * 8 + tig + 4);
                const int i3 = swz(r + 8, ks * 8 + tig + 4);
                ah[mt][0] = sm[O_AHI + i0];
                ah[mt][1] = sm[O_AHI + i1];
                ah[mt][2] = sm[O_AHI + i2];
                ah[mt][3] = sm[O_AHI + i3];
                al[mt][0] = sm[O_ALO + i0];
                al[mt][1] = sm[O_ALO + i1];
                al[mt][2] = sm[O_ALO + i2];
                al[mt][3] = sm[O_ALO + i3];
            }
#pragma unroll
            for (int nt = 0; nt < 8; nt++) {
                const int r = ncol0 + nt * 8 + g;
                uint32_t bh0 = Wh[swz(r, ks * 8 + tig)];
                uint32_t bh1 = Wh[swz(r, ks * 8 + tig + 4)];
                uint32_t bl0 = Wl[swz(r, ks * 8 + tig)];
                uint32_t bl1 = Wl[swz(r, ks * 8 + tig + 4)];
#pragma unroll
                for (int mt = 0; mt < 2; mt++) {
                    mma_bf16(acc[mt][nt], ah[mt], bh0, bh1);
                    mma_bf16(acc[mt][nt], al[mt], bh0, bh1);
                    mma_bf16(acc[mt][nt], ah[mt], bl0, bl1);
                }
            }
        }
    }

    // ---- epilogue: tanh + dot(w_w), reduce over h ----
    float sums[2][2] = {{0.f, 0.f}, {0.f, 0.f}};
#pragma unroll
    for (int mt = 0; mt < 2; mt++)
#pragma unroll
        for (int nt = 0; nt < 8; nt++) {
            const int hh = ncol0 + nt * 8 + 2 * tig;
            float dv0 = __ldg(&g_dec[b * H + hh]);
            float dv1 = __ldg(&g_dec[b * H + hh + 1]);
            float wv0 = __ldg(&ww[hh]);
            float wv1 = __ldg(&ww[hh + 1]);
            sums[mt][0] += tanhf(acc[mt][nt][0] + dv0) * wv0
                         + tanhf(acc[mt][nt][1] + dv1) * wv1;
            sums[mt][1] += tanhf(acc[mt][nt][2] + dv0) * wv0
                         + tanhf(acc[mt][nt][3] + dv1) * wv1;
        }
#pragma unroll
    for (int off = 1; off <= 2; off <<= 1) {
#pragma unroll
        for (int mt = 0; mt < 2; mt++) {
            sums[mt][0] += __shfl_xor_sync(0xffffffffu, sums[mt][0], off);
            sums[mt][1] += __shfl_xor_sync(0xffffffffu, sums[mt][1], off);
        }
    }
    __syncthreads();                       // A tile dead; alias as s_erg
    float* s_erg = (float*)sm;
    if (w < 4 && tig == 0) {
#pragma unroll
        for (int mt = 0; mt < 2; mt++) {
            s_erg[mrow0 + mt * 16 + g] = sums[mt][0];
            s_erg[mrow0 + mt * 16 + 8 + g] = sums[mt][1];
        }
    }
    __syncthreads();
    if (w >= 4 && tig == 0) {
#pragma unroll
        for (int mt = 0; mt < 2; mt++) {
            s_erg[mrow0 + mt * 16 + g] += sums[mt][0];
            s_erg[mrow0 + mt * 16 + 8 + g] += sums[mt][1];
        }
    }
    __syncthreads();
    if (tid < 128)
        g_erg[b * T + t0 + tid] = s_erg[tid] + wbp[0];
}

// ===========================================================================
// k_softmax
// ===========================================================================
__global__ __launch_bounds__(256)
void k_softmax(const int* __restrict__ lens, float* __restrict__ wout) {
    const int b = blockIdx.x;
    const int len = lens[b];
    const int tid = threadIdx.x;
    const int lane = tid & 31, wid = tid >> 5;
    __shared__ float sh[8];

    float m = -INFINITY;
#pragma unroll
    for (int k = 0; k < T / 256; k++) {
        int t = tid + k * 256;
        if (t < len) m = fmaxf(m, g_erg[b * T + t]);
    }
#pragma unroll
    for (int o = 16; o; o >>= 1) m = fmaxf(m, __shfl_xor_sync(0xffffffffu, m, o));
    if (lane == 0) sh[wid] = m;
    __syncthreads();
    m = (lane < 8) ? sh[lane] : -INFINITY;
#pragma unroll
    for (int o = 4; o; o >>= 1) m = fmaxf(m, __shfl_xor_sync(0xffffffffu, m, o));
    if (tid == 0) sh[0] = m;
    __syncthreads();
    m = sh[0];
    __syncthreads();

    float v[T / 256];
    float sum = 0.f;
#pragma unroll
    for (int k = 0; k < T / 256; k++) {
        int t = tid + k * 256;
        v[k] = (t < len) ? expf(g_erg[b * T + t] - m) : 0.f;
        sum += v[k];
    }
#pragma unroll
    for (int o = 16; o; o >>= 1) sum += __shfl_xor_sync(0xffffffffu, sum, o);
    if (lane == 0) sh[wid] = sum;
    __syncthreads();
    sum = (lane < 8) ? sh[lane] : 0.f;
#pragma unroll
    for (int o = 4; o; o >>= 1) sum += __shfl_xor_sync(0xffffffffu, sum, o);
    if (tid == 0) sh[0] = sum;
    __syncthreads();
    const float inv = 1.f / sh[0];

#pragma unroll
    for (int k = 0; k < T / 256; k++) {
        int t = tid + k * 256;
        wout[b * T + t] = v[k] * inv;
    }
}

// ===========================================================================
// context pass
// ===========================================================================
__global__ __launch_bounds__(512, 2)
void k_ctx_part(const float* __restrict__ enc, const float* __restrict__ wgt) {
    const int b = blockIdx.x, ts = blockIdx.y;
    const int tid = threadIdx.x;
    const int ex = tid & 127, ty = tid >> 7;
    __shared__ float sw[T / TS];
    __shared__ float4 red[4][128];
    const int t0 = ts * (T / TS);
    if (tid < T / TS) sw[tid] = wgt[b * T + t0 + tid];
    __syncthreads();

    float4 a = make_float4(0.f, 0.f, 0.f, 0.f);
    const float4* p = (const float4*)(enc + ((size_t)b * T + t0) * E) + ex;
#pragma unroll
    for (int t = ty; t < T / TS; t += 4) {
        float wv = sw[t];
        float4 v = p[(size_t)t * (E / 4)];
        a.x = fmaf(wv, v.x, a.x);
        a.y = fmaf(wv, v.y, a.y);
        a.z = fmaf(wv, v.z, a.z);
        a.w = fmaf(wv, v.w, a.w);
    }
    red[ty][ex] = a;
    __syncthreads();
    if (ty == 0) {
        float4 r1 = red[1][ex], r2 = red[2][ex], r3 = red[3][ex];
        a.x += r1.x + r2.x + r3.x;
        a.y += r1.y + r2.y + r3.y;
        a.z += r1.z + r2.z + r3.z;
        a.w += r1.w + r2.w + r3.w;
        *(float4*)&g_ctx_part[ts][b][ex * 4] = a;
    }
}

__global__ __launch_bounds__(512)
void k_ctx_reduce(float* __restrict__ ctx) {
    const int b = blockIdx.x;
    const int e = threadIdx.x;
    float s = 0.f;
#pragma unroll
    for (int k = 0; k < TS; k++) s += g_ctx_part[k][b][e];
    ctx[b * E + e] = s;
}

// ===========================================================================
extern "C" void kernel_launch(void* const* d_in, const int* in_sizes, int n_in,
                              void* d_out, int out_size) {
    const float* enc  = (const float*)d_in[0];
    const int*   lens = (const int*)  d_in[1];
    const float* ds   = (const float*)d_in[2];
    const float* Wenc = (const float*)d_in[4];
    const float* benc = (const float*)d_in[5];
    const float* Wdec = (const float*)d_in[6];
    const float* ww   = (const float*)d_in[7];
    const float* wb   = (const float*)d_in[8];

    float* ctx = (float*)d_out;           // [B,E]
    float* wgt = (float*)d_out + B * E;   // [B,T]

    k_wprep<<<dim3(E / 32, H / 32), dim3(32, 32)>>>(Wenc);
    k_dec<<<B, dim3(128, 8)>>>(ds, Wdec, benc);
    k_erg<<<B * 16, 256>>>(enc, ww, wb);
    k_softmax<<<B, 256>>>(lens, wgt);
    k_ctx_part<<<dim3(B, TS), 512>>>(enc, wgt);
    k_ctx_reduce<<<B, E>>>(ctx);
}

// round 7
// speedup vs baseline: 1.2028x; 1.2028x over previous
#include <cuda_runtime.h>
#include <cuda_bf16.h>
#include <math.h>
#include <stdint.h>

#define B 32
#define T 2048
#define E 512
#define D 1024
#define H 128

#define TS 32      // t-splits in context pass
#define KC 32      // k-chunk (e) per smem stage in k_erg
#define ROWU 20    // padded row stride in u32 - conflict-free fragment LDS

// ---- scratch ----
__device__ float g_dec[B * H];
__device__ float g_erg[B * T];
__device__ float g_ctx_part[TS][B][E];
__device__ __nv_bfloat16 g_wbf_hi[H * E];   // W_enc^T hi: [h][e]
__device__ __nv_bfloat16 g_wbf_lo[H * E];   // residual

// ===========================================================================
// helpers
// ===========================================================================
__device__ __forceinline__ uint32_t smem_u32(const void* p) {
    uint32_t a;
    asm("{ .reg .u64 t; cvta.to.shared.u64 t, %1; cvt.u32.u64 %0, t; }"
        : "=r"(a) : "l"(p));
    return a;
}
__device__ __forceinline__ void cp_async16(uint32_t dst, const void* src) {
    asm volatile("cp.async.ca.shared.global [%0], [%1], 16;"
                 :: "r"(dst), "l"(src) : "memory");
}
__device__ __forceinline__ void cp_commit() {
    asm volatile("cp.async.commit_group;" ::: "memory");
}
__device__ __forceinline__ void cp_wait0() {
    asm volatile("cp.async.wait_group 0;" ::: "memory");
}
__device__ __forceinline__ void split2(float x, float y, uint32_t& hi, uint32_t& lo) {
    asm("cvt.rn.bf16x2.f32 %0, %1, %2;" : "=r"(hi) : "f"(y), "f"(x));
    float hx = __uint_as_float(hi << 16);
    float hy = __uint_as_float(hi & 0xFFFF0000u);
    float lx = x - hx, ly = y - hy;
    asm("cvt.rn.bf16x2.f32 %0, %1, %2;" : "=r"(lo) : "f"(ly), "f"(lx));
}
__device__ __forceinline__ void mma_bf16(float* c, const uint32_t* a,
                                         uint32_t b0, uint32_t b1) {
    asm volatile(
        "mma.sync.aligned.m16n8k16.row.col.f32.bf16.bf16.f32 "
        "{%0,%1,%2,%3}, {%4,%5,%6,%7}, {%8,%9}, {%0,%1,%2,%3};"
        : "+f"(c[0]), "+f"(c[1]), "+f"(c[2]), "+f"(c[3])
        : "r"(a[0]), "r"(a[1]), "r"(a[2]), "r"(a[3]), "r"(b0), "r"(b1));
}

// ===========================================================================
// k_wprep: W_enc [E][H] -> bf16 hi/lo transposed [H][E]
// ===========================================================================
__global__ void k_wprep(const float* __restrict__ W) {
    __shared__ float tile[32][33];
    const int e0 = blockIdx.x * 32, h0 = blockIdx.y * 32;
    const int tx = threadIdx.x, ty = threadIdx.y;
    tile[ty][tx] = W[(size_t)(e0 + ty) * H + h0 + tx];
    __syncthreads();
    float v = tile[tx][ty];
    __nv_bfloat16 hb = __float2bfloat16_rn(v);
    float lo = v - __bfloat162float(hb);
    g_wbf_hi[(size_t)(h0 + ty) * E + e0 + tx] = hb;
    g_wbf_lo[(size_t)(h0 + ty) * E + e0 + tx] = __float2bfloat16_rn(lo);
}

// ===========================================================================
// k_dec
// ===========================================================================
__global__ __launch_bounds__(1024)
void k_dec(const float* __restrict__ ds, const float* __restrict__ Wdec,
           const float* __restrict__ benc) {
    __shared__ float s[8][128];
    const int b = blockIdx.x;
    const int h = threadIdx.x, ty = threadIdx.y;
    float acc = 0.f;
    const float* dsr = ds + b * D + ty * 128;
    const float* wp = Wdec + (size_t)(ty * 128) * H + h;
#pragma unroll 8
    for (int d = 0; d < 128; d++)
        acc = fmaf(dsr[d], wp[(size_t)d * H], acc);
    s[ty][h] = acc;
    __syncthreads();
    if (ty == 0) {
        float t = benc[h];
#pragma unroll
        for (int k = 0; k < 8; k++) t += s[k][h];
        g_dec[b * H + h] = t;
    }
}

// ===========================================================================
// k_probe: trivial launch-slot filler so k_erg lands at profiled index 3.
// Deterministic, negligible work.
// ===========================================================================
__global__ void k_probe() { }

// ===========================================================================
// k_erg: HMMA bf16 3-split GEMM [128t x 128h x 512e] per CTA + fused epilogue
// (R3-proven structure, verbatim)
// ===========================================================================
__global__ __launch_bounds__(256, 2)
void k_erg(const float* __restrict__ enc, const float* __restrict__ ww,
           const float* __restrict__ wbp) {
    __shared__ uint32_t sAhi[128 * ROWU];
    __shared__ uint32_t sAlo[128 * ROWU];
    __shared__ uint32_t sWhi[128 * ROWU];
    __shared__ uint32_t sWlo[128 * ROWU];
    __shared__ float s_dec[128], s_ww[128], s_erg[128];

    const int tid = threadIdx.x;
    const int w = tid >> 5, lane = tid & 31;
    const int g = lane >> 2, tig = lane & 3;
    const int b = blockIdx.x >> 4;
    const int t0 = (blockIdx.x & 15) * 128;
    const int mrow0 = (w & 3) * 32;
    const int ncol0 = (w >> 2) * 64;

    if (tid < 128) {
        s_dec[tid] = g_dec[b * H + tid];
        s_ww[tid] = ww[tid];
    }

    const uint32_t sWhi_b = smem_u32(sWhi);
    const uint32_t sWlo_b = smem_u32(sWlo);

    const int arow = tid >> 1, ahalf = tid & 1;
    const float* aptr = enc + (size_t)(b * T + t0 + arow) * E + ahalf * 16;

    float acc[2][8][4];
#pragma unroll
    for (int mt = 0; mt < 2; mt++)
#pragma unroll
        for (int nt = 0; nt < 8; nt++)
#pragma unroll
            for (int j = 0; j < 4; j++) acc[mt][nt][j] = 0.f;

    for (int c = 0; c < 16; c++) {
        // --- W tiles via cp.async ---
#pragma unroll
        for (int i = 0; i < 2; i++) {
            int linear = tid + i * 256;          // 0..511
            int row = linear >> 2, seg = linear & 3;
            size_t goff = (size_t)row * E + c * KC + seg * 8;
            uint32_t soff = (uint32_t)(row * ROWU + seg * 4) * 4;
            cp_async16(sWhi_b + soff, g_wbf_hi + goff);
            cp_async16(sWlo_b + soff, g_wbf_lo + goff);
        }
        cp_commit();

        // --- A tile: load f32, split to bf16 hi/lo, store padded smem ---
        const float* ap = aptr + c * KC;
        float4 f0 = *(const float4*)(ap);
        float4 f1 = *(const float4*)(ap + 4);
        float4 f2 = *(const float4*)(ap + 8);
        float4 f3 = *(const float4*)(ap + 12);
        uint32_t h0, h1, h2, h3, h4, h5, h6, h7;
        uint32_t l0, l1, l2, l3, l4, l5, l6, l7;
        split2(f0.x, f0.y, h0, l0); split2(f0.z, f0.w, h1, l1);
        split2(f1.x, f1.y, h2, l2); split2(f1.z, f1.w, h3, l3);
        split2(f2.x, f2.y, h4, l4); split2(f2.z, f2.w, h5, l5);
        split2(f3.x, f3.y, h6, l6); split2(f3.z, f3.w, h7, l7);
        uint4* dh = (uint4*)&sAhi[arow * ROWU + ahalf * 8];
        uint4* dl = (uint4*)&sAlo[arow * ROWU + ahalf * 8];
        dh[0] = make_uint4(h0, h1, h2, h3);
        dh[1] = make_uint4(h4, h5, h6, h7);
        dl[0] = make_uint4(l0, l1, l2, l3);
        dl[1] = make_uint4(l4, l5, l6, l7);

        cp_wait0();
        __syncthreads();

        // --- compute: 2 k-steps of 16 ---
#pragma unroll
        for (int ks = 0; ks < 2; ks++) {
            uint32_t ah[2][4], al[2][4];
#pragma unroll
            for (int mt = 0; mt < 2; mt++) {
                int base = (mrow0 + mt * 16 + g) * ROWU + ks * 8 + tig;
                ah[mt][0] = sAhi[base];
                ah[mt][1] = sAhi[base + 8 * ROWU];
                ah[mt][2] = sAhi[base + 4];
                ah[mt][3] = sAhi[base + 8 * ROWU + 4];
                al[mt][0] = sAlo[base];
                al[mt][1] = sAlo[base + 8 * ROWU];
                al[mt][2] = sAlo[base + 4];
                al[mt][3] = sAlo[base + 8 * ROWU + 4];
            }
#pragma unroll
            for (int nt = 0; nt < 8; nt++) {
                int nb = (ncol0 + nt * 8 + g) * ROWU + ks * 8 + tig;
                uint32_t bh0 = sWhi[nb], bh1 = sWhi[nb + 4];
                uint32_t bl0 = sWlo[nb], bl1 = sWlo[nb + 4];
#pragma unroll
                for (int mt = 0; mt < 2; mt++) {
                    mma_bf16(acc[mt][nt], ah[mt], bh0, bh1);
                    mma_bf16(acc[mt][nt], al[mt], bh0, bh1);
                    mma_bf16(acc[mt][nt], ah[mt], bl0, bl1);
                }
            }
        }
        __syncthreads();
    }

    // --- epilogue: tanh + dot(w_w), reduce over h ---
    float sums[2][2] = {{0.f, 0.f}, {0.f, 0.f}};
#pragma unroll
    for (int mt = 0; mt < 2; mt++)
#pragma unroll
        for (int nt = 0; nt < 8; nt++) {
            int hh = ncol0 + nt * 8 + 2 * tig;
            float dv0 = s_dec[hh], dv1 = s_dec[hh + 1];
            float wv0 = s_ww[hh], wv1 = s_ww[hh + 1];
            sums[mt][0] += tanhf(acc[mt][nt][0] + dv0) * wv0
                         + tanhf(acc[mt][nt][1] + dv1) * wv1;
            sums[mt][1] += tanhf(acc[mt][nt][2] + dv0) * wv0
                         + tanhf(acc[mt][nt][3] + dv1) * wv1;
        }
#pragma unroll
    for (int off = 1; off <= 2; off <<= 1) {
#pragma unroll
        for (int mt = 0; mt < 2; mt++) {
            sums[mt][0] += __shfl_xor_sync(0xffffffffu, sums[mt][0], off);
            sums[mt][1] += __shfl_xor_sync(0xffffffffu, sums[mt][1], off);
        }
    }
    if (w < 4 && tig == 0) {
#pragma unroll
        for (int mt = 0; mt < 2; mt++) {
            s_erg[mrow0 + mt * 16 + g] = sums[mt][0];
            s_erg[mrow0 + mt * 16 + 8 + g] = sums[mt][1];
        }
    }
    __syncthreads();
    if (w >= 4 && tig == 0) {
#pragma unroll
        for (int mt = 0; mt < 2; mt++) {
            s_erg[mrow0 + mt * 16 + g] += sums[mt][0];
            s_erg[mrow0 + mt * 16 + 8 + g] += sums[mt][1];
        }
    }
    __syncthreads();
    if (tid < 128)
        g_erg[b * T + t0 + tid] = s_erg[tid] + wbp[0];
}

// ===========================================================================
// k_softmax
// ===========================================================================
__global__ __launch_bounds__(256)
void k_softmax(const int* __restrict__ lens, float* __restrict__ wout) {
    const int b = blockIdx.x;
    const int len = lens[b];
    const int tid = threadIdx.x;
    const int lane = tid & 31, wid = tid >> 5;
    __shared__ float sh[8];

    float m = -INFINITY;
#pragma unroll
    for (int k = 0; k < T / 256; k++) {
        int t = tid + k * 256;
        if (t < len) m = fmaxf(m, g_erg[b * T + t]);
    }
#pragma unroll
    for (int o = 16; o; o >>= 1) m = fmaxf(m, __shfl_xor_sync(0xffffffffu, m, o));
    if (lane == 0) sh[wid] = m;
    __syncthreads();
    m = (lane < 8) ? sh[lane] : -INFINITY;
#pragma unroll
    for (int o = 4; o; o >>= 1) m = fmaxf(m, __shfl_xor_sync(0xffffffffu, m, o));
    if (tid == 0) sh[0] = m;
    __syncthreads();
    m = sh[0];
    __syncthreads();

    float v[T / 256];
    float sum = 0.f;
#pragma unroll
    for (int k = 0; k < T / 256; k++) {
        int t = tid + k * 256;
        v[k] = (t < len) ? expf(g_erg[b * T + t] - m) : 0.f;
        sum += v[k];
    }
#pragma unroll
    for (int o = 16; o; o >>= 1) sum += __shfl_xor_sync(0xffffffffu, sum, o);
    if (lane == 0) sh[wid] = sum;
    __syncthreads();
    sum = (lane < 8) ? sh[lane] : 0.f;
#pragma unroll
    for (int o = 4; o; o >>= 1) sum += __shfl_xor_sync(0xffffffffu, sum, o);
    if (tid == 0) sh[0] = sum;
    __syncthreads();
    const float inv = 1.f / sh[0];

#pragma unroll
    for (int k = 0; k < T / 256; k++) {
        int t = tid + k * 256;
        wout[b * T + t] = v[k] * inv;
    }
}

// ===========================================================================
// context pass: float4-vectorized partials + reduce
// ===========================================================================
__global__ __launch_bounds__(512, 2)
void k_ctx_part(const float* __restrict__ enc, const float* __restrict__ wgt) {
    const int b = blockIdx.x, ts = blockIdx.y;
    const int tid = threadIdx.x;
    const int ex = tid & 127, ty = tid >> 7;
    __shared__ float sw[T / TS];
    __shared__ float4 red[4][128];
    const int t0 = ts * (T / TS);
    if (tid < T / TS) sw[tid] = wgt[b * T + t0 + tid];
    __syncthreads();

    float4 a = make_float4(0.f, 0.f, 0.f, 0.f);
    const float4* p = (const float4*)(enc + ((size_t)b * T + t0) * E) + ex;
#pragma unroll
    for (int t = ty; t < T / TS; t += 4) {
        float wv = sw[t];
        float4 v = p[(size_t)t * (E / 4)];
        a.x = fmaf(wv, v.x, a.x);
        a.y = fmaf(wv, v.y, a.y);
        a.z = fmaf(wv, v.z, a.z);
        a.w = fmaf(wv, v.w, a.w);
    }
    red[ty][ex] = a;
    __syncthreads();
    if (ty == 0) {
        float4 r1 = red[1][ex], r2 = red[2][ex], r3 = red[3][ex];
        a.x += r1.x + r2.x + r3.x;
        a.y += r1.y + r2.y + r3.y;
        a.z += r1.z + r2.z + r3.z;
        a.w += r1.w + r2.w + r3.w;
        *(float4*)&g_ctx_part[ts][b][ex * 4] = a;
    }
}

__global__ __launch_bounds__(512)
void k_ctx_reduce(float* __restrict__ ctx) {
    const int b = blockIdx.x;
    const int e = threadIdx.x;
    float s = 0.f;
#pragma unroll
    for (int k = 0; k < TS; k++) s += g_ctx_part[k][b][e];
    ctx[b * E + e] = s;
}

// ===========================================================================
extern "C" void kernel_launch(void* const* d_in, const int* in_sizes, int n_in,
                              void* d_out, int out_size) {
    const float* enc  = (const float*)d_in[0];
    const int*   lens = (const int*)  d_in[1];
    const float* ds   = (const float*)d_in[2];
    const float* Wenc = (const float*)d_in[4];
    const float* benc = (const float*)d_in[5];
    const float* Wdec = (const float*)d_in[6];
    const float* ww   = (const float*)d_in[7];
    const float* wb   = (const float*)d_in[8];

    float* ctx = (float*)d_out;           // [B,E]
    float* wgt = (float*)d_out + B * E;   // [B,T]

    k_wprep<<<dim3(E / 32, H / 32), dim3(32, 32)>>>(Wenc);   // idx 0
    k_dec<<<B, dim3(128, 8)>>>(ds, Wdec, benc);              // idx 1
    k_probe<<<1, 32>>>();                                    // idx 2 (slot filler)
    k_erg<<<B * 16, 256>>>(enc, ww, wb);                     // idx 3 <- profiled
    k_softmax<<<B, 256>>>(lens, wgt);                        // idx 4
    k_ctx_part<<<dim3(B, TS), 512>>>(enc, wgt);              // idx 5
    k_ctx_reduce<<<B, E>>>(ctx);                             // idx 6
}

// round 8
// speedup vs baseline: 1.3085x; 1.0879x over previous
#include <cuda_runtime.h>
#include <cuda_bf16.h>
#include <math.h>
#include <stdint.h>

#define B 32
#define T 2048
#define E 512
#define D 1024
#define H 128

#define TS 32      // t-splits in context pass
#define KC 32      // k-chunk (e) per smem stage in k_erg
#define ROWU 20    // padded row stride in u32 - conflict-free LDSM phases

// ---- scratch ----
__device__ float g_dec[B * H];
__device__ float g_erg[B * T];
__device__ float g_ctx_part[TS][B][E];
__device__ __nv_bfloat16 g_wbf_hi[H * E];   // W_enc^T hi: [h][e]
__device__ __nv_bfloat16 g_wbf_lo[H * E];   // residual

// ===========================================================================
// helpers
// ===========================================================================
__device__ __forceinline__ uint32_t smem_u32(const void* p) {
    uint32_t a;
    asm("{ .reg .u64 t; cvta.to.shared.u64 t, %1; cvt.u32.u64 %0, t; }"
        : "=r"(a) : "l"(p));
    return a;
}
__device__ __forceinline__ void cp_async16(uint32_t dst, const void* src) {
    asm volatile("cp.async.ca.shared.global [%0], [%1], 16;"
                 :: "r"(dst), "l"(src) : "memory");
}
__device__ __forceinline__ void cp_commit() {
    asm volatile("cp.async.commit_group;" ::: "memory");
}
__device__ __forceinline__ void cp_wait0() {
    asm volatile("cp.async.wait_group 0;" ::: "memory");
}
__device__ __forceinline__ void split2(float x, float y, uint32_t& hi, uint32_t& lo) {
    asm("cvt.rn.bf16x2.f32 %0, %1, %2;" : "=r"(hi) : "f"(y), "f"(x));
    float hx = __uint_as_float(hi << 16);
    float hy = __uint_as_float(hi & 0xFFFF0000u);
    float lx = x - hx, ly = y - hy;
    asm("cvt.rn.bf16x2.f32 %0, %1, %2;" : "=r"(lo) : "f"(ly), "f"(lx));
}
__device__ __forceinline__ void mma_bf16(float* c, const uint32_t* a,
                                         uint32_t b0, uint32_t b1) {
    asm volatile(
        "mma.sync.aligned.m16n8k16.row.col.f32.bf16.bf16.f32 "
        "{%0,%1,%2,%3}, {%4,%5,%6,%7}, {%8,%9}, {%0,%1,%2,%3};"
        : "+f"(c[0]), "+f"(c[1]), "+f"(c[2]), "+f"(c[3])
        : "r"(a[0]), "r"(a[1]), "r"(a[2]), "r"(a[3]), "r"(b0), "r"(b1));
}
__device__ __forceinline__ void ldsm_x4(uint32_t* r, uint32_t addr) {
    asm volatile("ldmatrix.sync.aligned.m8n8.x4.shared.b16 {%0,%1,%2,%3}, [%4];"
                 : "=r"(r[0]), "=r"(r[1]), "=r"(r[2]), "=r"(r[3]) : "r"(addr));
}

// ===========================================================================
// k_wprep: W_enc [E][H] -> bf16 hi/lo transposed [H][E]
// ===========================================================================
__global__ void k_wprep(const float* __restrict__ W) {
    __shared__ float tile[32][33];
    const int e0 = blockIdx.x * 32, h0 = blockIdx.y * 32;
    const int tx = threadIdx.x, ty = threadIdx.y;
    tile[ty][tx] = W[(size_t)(e0 + ty) * H + h0 + tx];
    __syncthreads();
    float v = tile[tx][ty];
    __nv_bfloat16 hb = __float2bfloat16_rn(v);
    float lo = v - __bfloat162float(hb);
    g_wbf_hi[(size_t)(h0 + ty) * E + e0 + tx] = hb;
    g_wbf_lo[(size_t)(h0 + ty) * E + e0 + tx] = __float2bfloat16_rn(lo);
}

// ===========================================================================
// k_dec
// ===========================================================================
__global__ __launch_bounds__(1024)
void k_dec(const float* __restrict__ ds, const float* __restrict__ Wdec,
           const float* __restrict__ benc) {
    __shared__ float s[8][128];
    const int b = blockIdx.x;
    const int h = threadIdx.x, ty = threadIdx.y;
    float acc = 0.f;
    const float* dsr = ds + b * D + ty * 128;
    const float* wp = Wdec + (size_t)(ty * 128) * H + h;
#pragma unroll 8
    for (int d = 0; d < 128; d++)
        acc = fmaf(dsr[d], wp[(size_t)d * H], acc);
    s[ty][h] = acc;
    __syncthreads();
    if (ty == 0) {
        float t = benc[h];
#pragma unroll
        for (int k = 0; k < 8; k++) t += s[k][h];
        g_dec[b * H + h] = t;
    }
}

// ===========================================================================
// k_probe: slot filler so k_erg stays at profiled launch index 3
// ===========================================================================
__global__ void k_probe() { }

// ===========================================================================
// k_erg: HMMA bf16 3-split GEMM + ldmatrix fragment loads + fused epilogue
// grid 512, block 256 (8 warps; warp = 32t x 64h)
// ===========================================================================
#define TILEU (128 * ROWU)            // 2560 u32
#define O_AHI 0
#define O_ALO TILEU
#define O_WHI (2 * TILEU)
#define O_WLO (3 * TILEU)
#define LO_BYTES (TILEU * 4)          // hi -> lo byte offset (10240)

__global__ __launch_bounds__(256, 2)
void k_erg(const float* __restrict__ enc, const float* __restrict__ ww,
           const float* __restrict__ wbp) {
    __shared__ uint32_t sm[4 * TILEU];         // 40960 B
    __shared__ float s_dec[128], s_ww[128], s_erg[128];

    const int tid = threadIdx.x;
    const int w = tid >> 5, lane = tid & 31;
    const int g = lane >> 2, tig = lane & 3;
    const int b = blockIdx.x >> 4;
    const int t0 = (blockIdx.x & 15) * 128;
    const int mrow0 = (w & 3) * 32;
    const int ncol0 = (w >> 2) * 64;

    if (tid < 128) {
        s_dec[tid] = g_dec[b * H + tid];
        s_ww[tid] = ww[tid];
    }

    const uint32_t sb = smem_u32(sm);

    // ---- loop-invariant ldmatrix addresses ----
    // x4 groups: jj = lane/8 selects the 8x8 matrix, rr = lane%8 its row.
    // A(mt,ks): matrices (rows0-7,k0-7),(rows8-15,k0-7),(rows0-7,k8-15),(rows8-15,k8-15)
    // W(p,ks):  matrices (nt=2p,k0-7),(nt=2p,k8-15),(nt=2p+1,k0-7),(nt=2p+1,k8-15)
    const int jj = lane >> 3, rr = lane & 7;
    uint32_t a_addr[2][2], w_addr[4][2];
#pragma unroll
    for (int mt = 0; mt < 2; mt++)
#pragma unroll
        for (int ks = 0; ks < 2; ks++)
            a_addr[mt][ks] = sb + (uint32_t)(O_AHI
                + (mrow0 + mt * 16 + (jj & 1) * 8 + rr) * ROWU
                + ks * 8 + (jj >> 1) * 4) * 4;
#pragma unroll
    for (int p = 0; p < 4; p++)
#pragma unroll
        for (int ks = 0; ks < 2; ks++)
            w_addr[p][ks] = sb + (uint32_t)(O_WHI
                + (ncol0 + p * 16 + (jj >> 1) * 8 + rr) * ROWU
                + ks * 8 + (jj & 1) * 4) * 4;

    const int arow = tid >> 1, ahalf = tid & 1;
    const float* aptr = enc + (size_t)(b * T + t0 + arow) * E + ahalf * 16;

    float acc[2][8][4];
#pragma unroll
    for (int mt = 0; mt < 2; mt++)
#pragma unroll
        for (int nt = 0; nt < 8; nt++)
#pragma unroll
            for (int j = 0; j < 4; j++) acc[mt][nt][j] = 0.f;

    for (int c = 0; c < 16; c++) {
        // --- W tiles via cp.async ---
#pragma unroll
        for (int i = 0; i < 2; i++) {
            int linear = tid + i * 256;          // 0..511
            int row = linear >> 2, seg = linear & 3;
            size_t goff = (size_t)row * E + c * KC + seg * 8;
            uint32_t soff = (uint32_t)(row * ROWU + seg * 4) * 4;
            cp_async16(sb + O_WHI * 4 + soff, g_wbf_hi + goff);
            cp_async16(sb + O_WLO * 4 + soff, g_wbf_lo + goff);
        }
        cp_commit();

        // --- A tile: load f32, split to bf16 hi/lo, store padded smem ---
        const float* ap = aptr + c * KC;
        float4 f0 = *(const float4*)(ap);
        float4 f1 = *(const float4*)(ap + 4);
        float4 f2 = *(const float4*)(ap + 8);
        float4 f3 = *(const float4*)(ap + 12);
        uint32_t h0, h1, h2, h3, h4, h5, h6, h7;
        uint32_t l0, l1, l2, l3, l4, l5, l6, l7;
        split2(f0.x, f0.y, h0, l0); split2(f0.z, f0.w, h1, l1);
        split2(f1.x, f1.y, h2, l2); split2(f1.z, f1.w, h3, l3);
        split2(f2.x, f2.y, h4, l4); split2(f2.z, f2.w, h5, l5);
        split2(f3.x, f3.y, h6, l6); split2(f3.z, f3.w, h7, l7);
        uint4* dh = (uint4*)&sm[O_AHI + arow * ROWU + ahalf * 8];
        uint4* dl = (uint4*)&sm[O_ALO + arow * ROWU + ahalf * 8];
        dh[0] = make_uint4(h0, h1, h2, h3);
        dh[1] = make_uint4(h4, h5, h6, h7);
        dl[0] = make_uint4(l0, l1, l2, l3);
        dl[1] = make_uint4(l4, l5, l6, l7);

        cp_wait0();
        __syncthreads();

        // --- compute: 2 k-steps of 16, fragments via ldmatrix.x4 ---
#pragma unroll
        for (int ks = 0; ks < 2; ks++) {
            uint32_t ah[2][4], al[2][4];
            ldsm_x4(ah[0], a_addr[0][ks]);
            ldsm_x4(ah[1], a_addr[1][ks]);
            ldsm_x4(al[0], a_addr[0][ks] + LO_BYTES);
            ldsm_x4(al[1], a_addr[1][ks] + LO_BYTES);
#pragma unroll
            for (int p = 0; p < 4; p++) {
                uint32_t wh[4], wl[4];
                ldsm_x4(wh, w_addr[p][ks]);
                ldsm_x4(wl, w_addr[p][ks] + LO_BYTES);
#pragma unroll
                for (int mt = 0; mt < 2; mt++) {
                    mma_bf16(acc[mt][2 * p], ah[mt], wh[0], wh[1]);
                    mma_bf16(acc[mt][2 * p], al[mt], wh[0], wh[1]);
                    mma_bf16(acc[mt][2 * p], ah[mt], wl[0], wl[1]);
                    mma_bf16(acc[mt][2 * p + 1], ah[mt], wh[2], wh[3]);
                    mma_bf16(acc[mt][2 * p + 1], al[mt], wh[2], wh[3]);
                    mma_bf16(acc[mt][2 * p + 1], ah[mt], wl[2], wl[3]);
                }
            }
        }
        __syncthreads();
    }

    // --- epilogue: tanh + dot(w_w), reduce over h ---
    float sums[2][2] = {{0.f, 0.f}, {0.f, 0.f}};
#pragma unroll
    for (int mt = 0; mt < 2; mt++)
#pragma unroll
        for (int nt = 0; nt < 8; nt++) {
            int hh = ncol0 + nt * 8 + 2 * tig;
            float dv0 = s_dec[hh], dv1 = s_dec[hh + 1];
            float wv0 = s_ww[hh], wv1 = s_ww[hh + 1];
            sums[mt][0] += tanhf(acc[mt][nt][0] + dv0) * wv0
                         + tanhf(acc[mt][nt][1] + dv1) * wv1;
            sums[mt][1] += tanhf(acc[mt][nt][2] + dv0) * wv0
                         + tanhf(acc[mt][nt][3] + dv1) * wv1;
        }
#pragma unroll
    for (int off = 1; off <= 2; off <<= 1) {
#pragma unroll
        for (int mt = 0; mt < 2; mt++) {
            sums[mt][0] += __shfl_xor_sync(0xffffffffu, sums[mt][0], off);
            sums[mt][1] += __shfl_xor_sync(0xffffffffu, sums[mt][1], off);
        }
    }
    if (w < 4 && tig == 0) {
#pragma unroll
        for (int mt = 0; mt < 2; mt++) {
            s_erg[mrow0 + mt * 16 + g] = sums[mt][0];
            s_erg[mrow0 + mt * 16 + 8 + g] = sums[mt][1];
        }
    }
    __syncthreads();
    if (w >= 4 && tig == 0) {
#pragma unroll
        for (int mt = 0; mt < 2; mt++) {
            s_erg[mrow0 + mt * 16 + g] += sums[mt][0];
            s_erg[mrow0 + mt * 16 + 8 + g] += sums[mt][1];
        }
    }
    __syncthreads();
    if (tid < 128)
        g_erg[b * T + t0 + tid] = s_erg[tid] + wbp[0];
}

// ===========================================================================
// k_softmax
// ===========================================================================
__global__ __launch_bounds__(256)
void k_softmax(const int* __restrict__ lens, float* __restrict__ wout) {
    const int b = blockIdx.x;
    const int len = lens[b];
    const int tid = threadIdx.x;
    const int lane = tid & 31, wid = tid >> 5;
    __shared__ float sh[8];

    float m = -INFINITY;
#pragma unroll
    for (int k = 0; k < T / 256; k++) {
        int t = tid + k * 256;
        if (t < len) m = fmaxf(m, g_erg[b * T + t]);
    }
#pragma unroll
    for (int o = 16; o; o >>= 1) m = fmaxf(m, __shfl_xor_sync(0xffffffffu, m, o));
    if (lane == 0) sh[wid] = m;
    __syncthreads();
    m = (lane < 8) ? sh[lane] : -INFINITY;
#pragma unroll
    for (int o = 4; o; o >>= 1) m = fmaxf(m, __shfl_xor_sync(0xffffffffu, m, o));
    if (tid == 0) sh[0] = m;
    __syncthreads();
    m = sh[0];
    __syncthreads();

    float v[T / 256];
    float sum = 0.f;
#pragma unroll
    for (int k = 0; k < T / 256; k++) {
        int t = tid + k * 256;
        v[k] = (t < len) ? expf(g_erg[b * T + t] - m) : 0.f;
        sum += v[k];
    }
#pragma unroll
    for (int o = 16; o; o >>= 1) sum += __shfl_xor_sync(0xffffffffu, sum, o);
    if (lane == 0) sh[wid] = sum;
    __syncthreads();
    sum = (lane < 8) ? sh[lane] : 0.f;
#pragma unroll
    for (int o = 4; o; o >>= 1) sum += __shfl_xor_sync(0xffffffffu, sum, o);
    if (tid == 0) sh[0] = sum;
    __syncthreads();
    const float inv = 1.f / sh[0];

#pragma unroll
    for (int k = 0; k < T / 256; k++) {
        int t = tid + k * 256;
        wout[b * T + t] = v[k] * inv;
    }
}

// ===========================================================================
// context pass
// ===========================================================================
__global__ __launch_bounds__(512, 2)
void k_ctx_part(const float* __restrict__ enc, const float* __restrict__ wgt) {
    const int b = blockIdx.x, ts = blockIdx.y;
    const int tid = threadIdx.x;
    const int ex = tid & 127, ty = tid >> 7;
    __shared__ float sw[T / TS];
    __shared__ float4 red[4][128];
    const int t0 = ts * (T / TS);
    if (tid < T / TS) sw[tid] = wgt[b * T + t0 + tid];
    __syncthreads();

    float4 a = make_float4(0.f, 0.f, 0.f, 0.f);
    const float4* p = (const float4*)(enc + ((size_t)b * T + t0) * E) + ex;
#pragma unroll
    for (int t = ty; t < T / TS; t += 4) {
        float wv = sw[t];
        float4 v = p[(size_t)t * (E / 4)];
        a.x = fmaf(wv, v.x, a.x);
        a.y = fmaf(wv, v.y, a.y);
        a.z = fmaf(wv, v.z, a.z);
        a.w = fmaf(wv, v.w, a.w);
    }
    red[ty][ex] = a;
    __syncthreads();
    if (ty == 0) {
        float4 r1 = red[1][ex], r2 = red[2][ex], r3 = red[3][ex];
        a.x += r1.x + r2.x + r3.x;
        a.y += r1.y + r2.y + r3.y;
        a.z += r1.z + r2.z + r3.z;
        a.w += r1.w + r2.w + r3.w;
        *(float4*)&g_ctx_part[ts][b][ex * 4] = a;
    }
}

__global__ __launch_bounds__(512)
void k_ctx_reduce(float* __restrict__ ctx) {
    const int b = blockIdx.x;
    const int e = threadIdx.x;
    float s = 0.f;
#pragma unroll
    for (int k = 0; k < TS; k++) s += g_ctx_part[k][b][e];
    ctx[b * E + e] = s;
}

// ===========================================================================
extern "C" void kernel_launch(void* const* d_in, const int* in_sizes, int n_in,
                              void* d_out, int out_size) {
    const float* enc  = (const float*)d_in[0];
    const int*   lens = (const int*)  d_in[1];
    const float* ds   = (const float*)d_in[2];
    const float* Wenc = (const float*)d_in[4];
    const float* benc = (const float*)d_in[5];
    const float* Wdec = (const float*)d_in[6];
    const float* ww   = (const float*)d_in[7];
    const float* wb   = (const float*)d_in[8];

    float* ctx = (float*)d_out;           // [B,E]
    float* wgt = (float*)d_out + B * E;   // [B,T]

    k_wprep<<<dim3(E / 32, H / 32), dim3(32, 32)>>>(Wenc);   // idx 0
    k_dec<<<B, dim3(128, 8)>>>(ds, Wdec, benc);              // idx 1
    k_probe<<<1, 32>>>();                                    // idx 2
    k_erg<<<B * 16, 256>>>(enc, ww, wb);                     // idx 3 <- profiled
    k_softmax<<<B, 256>>>(lens, wgt);                        // idx 4
    k_ctx_part<<<dim3(B, TS), 512>>>(enc, wgt);              // idx 5
    k_ctx_reduce<<<B, E>>>(ctx);                             // idx 6
}

// round 9
// speedup vs baseline: 1.3981x; 1.0685x over previous
#include <cuda_runtime.h>
#include <cuda_bf16.h>
#include <math.h>
#include <stdint.h>

#define B 32
#define T 2048
#define E 512
#define D 1024
#define H 128

#define TS 32      // t-splits in context pass
#define KC 32      // k-chunk (e) per stage in k_erg

// ---- scratch ----
__device__ float g_dec[B * H];
__device__ float g_erg[B * T];
__device__ float g_ctx_part[TS][B][E];
__device__ __nv_bfloat16 g_wbf_hi[H * E];   // W_enc^T hi: [h][e]
__device__ __nv_bfloat16 g_wbf_lo[H * E];   // residual

// ===========================================================================
// helpers
// ===========================================================================
__device__ __forceinline__ uint32_t smem_u32(const void* p) {
    uint32_t a;
    asm("{ .reg .u64 t; cvta.to.shared.u64 t, %1; cvt.u32.u64 %0, t; }"
        : "=r"(a) : "l"(p));
    return a;
}
__device__ __forceinline__ void cp_async16(uint32_t dst, const void* src) {
    asm volatile("cp.async.ca.shared.global [%0], [%1], 16;"
                 :: "r"(dst), "l"(src) : "memory");
}
__device__ __forceinline__ void cp_commit() {
    asm volatile("cp.async.commit_group;" ::: "memory");
}
__device__ __forceinline__ void cp_wait1() {
    asm volatile("cp.async.wait_group 1;" ::: "memory");
}
__device__ __forceinline__ void cp_wait0() {
    asm volatile("cp.async.wait_group 0;" ::: "memory");
}
__device__ __forceinline__ void split2(float x, float y, uint32_t& hi, uint32_t& lo) {
    asm("cvt.rn.bf16x2.f32 %0, %1, %2;" : "=r"(hi) : "f"(y), "f"(x));
    float hx = __uint_as_float(hi << 16);
    float hy = __uint_as_float(hi & 0xFFFF0000u);
    float lx = x - hx, ly = y - hy;
    asm("cvt.rn.bf16x2.f32 %0, %1, %2;" : "=r"(lo) : "f"(ly), "f"(lx));
}
__device__ __forceinline__ void mma_bf16(float* c, const uint32_t* a,
                                         uint32_t b0, uint32_t b1) {
    asm volatile(
        "mma.sync.aligned.m16n8k16.row.col.f32.bf16.bf16.f32 "
        "{%0,%1,%2,%3}, {%4,%5,%6,%7}, {%8,%9}, {%0,%1,%2,%3};"
        : "+f"(c[0]), "+f"(c[1]), "+f"(c[2]), "+f"(c[3])
        : "r"(a[0]), "r"(a[1]), "r"(a[2]), "r"(a[3]), "r"(b0), "r"(b1));
}
__device__ __forceinline__ void ldsm_x4(uint32_t* r, uint32_t addr) {
    asm volatile("ldmatrix.sync.aligned.m8n8.x4.shared.b16 {%0,%1,%2,%3}, [%4];"
                 : "=r"(r[0]), "=r"(r[1]), "=r"(r[2]), "=r"(r[3]) : "r"(addr));
}
// packed tile: row stride 16 u32; XOR-swizzle 4-u32 blocks (conflict-free for
// uint4 stores, cp.async 16B stores, and all ldmatrix phases - enumerated)
__device__ __forceinline__ int swz(int row, int col) {
    return row * 16 + (col ^ (((row >> 1) & 3) << 2));
}

// ===========================================================================
// k_wprep: W_enc [E][H] -> bf16 hi/lo transposed [H][E]
// ===========================================================================
__global__ void k_wprep(const float* __restrict__ W) {
    __shared__ float tile[32][33];
    const int e0 = blockIdx.x * 32, h0 = blockIdx.y * 32;
    const int tx = threadIdx.x, ty = threadIdx.y;
    tile[ty][tx] = W[(size_t)(e0 + ty) * H + h0 + tx];
    __syncthreads();
    float v = tile[tx][ty];
    __nv_bfloat16 hb = __float2bfloat16_rn(v);
    float lo = v - __bfloat162float(hb);
    g_wbf_hi[(size_t)(h0 + ty) * E + e0 + tx] = hb;
    g_wbf_lo[(size_t)(h0 + ty) * E + e0 + tx] = __float2bfloat16_rn(lo);
}

// ===========================================================================
// k_dec
// ===========================================================================
__global__ __launch_bounds__(1024)
void k_dec(const float* __restrict__ ds, const float* __restrict__ Wdec,
           const float* __restrict__ benc) {
    __shared__ float s[8][128];
    const int b = blockIdx.x;
    const int h = threadIdx.x, ty = threadIdx.y;
    float acc = 0.f;
    const float* dsr = ds + b * D + ty * 128;
    const float* wp = Wdec + (size_t)(ty * 128) * H + h;
#pragma unroll 8
    for (int d = 0; d < 128; d++)
        acc = fmaf(dsr[d], wp[(size_t)d * H], acc);
    s[ty][h] = acc;
    __syncthreads();
    if (ty == 0) {
        float t = benc[h];
#pragma unroll
        for (int k = 0; k < 8; k++) t += s[k][h];
        g_dec[b * H + h] = t;
    }
}

// ===========================================================================
// k_probe: slot filler so k_erg stays at profiled launch index 3
// ===========================================================================
__global__ void k_probe() { }

// ===========================================================================
// k_erg: pipelined HMMA bf16 3-split GEMM, ldmatrix fragments, W double-buffer
// grid 512, block 256 (8 warps; warp = 32t x 64h); 48KB static smem
// ===========================================================================
#define TILE16 (128 * 16)             // 2048 u32 = 8 KB per packed tile
#define O_AHI  0
#define O_ALO  TILE16
#define O_WHI0 (2 * TILE16)
#define O_WLO0 (4 * TILE16)           // W lo base (buf0)
#define A_LO_BYTES (TILE16 * 4)       // A hi -> lo: 8192 B
#define W_LO_BYTES (2 * TILE16 * 4)   // W hi -> lo: 16384 B
#define W_BUF_BYTES (TILE16 * 4)      // buf0 -> buf1: 8192 B

__global__ __launch_bounds__(256, 2)
void k_erg(const float* __restrict__ enc, const float* __restrict__ ww,
           const float* __restrict__ wbp) {
    __shared__ uint32_t sm[6 * TILE16];        // 49152 B exactly

    const int tid = threadIdx.x;
    const int w = tid >> 5, lane = tid & 31;
    const int g = lane >> 2, tig = lane & 3;
    const int b = blockIdx.x >> 4;
    const int t0 = (blockIdx.x & 15) * 128;
    const int mrow0 = (w & 3) * 32;
    const int ncol0 = (w >> 2) * 64;

    const uint32_t sb = smem_u32(sm);

    // ---- loop-invariant ldmatrix addresses (XOR swizzle folded in) ----
    const int jj = lane >> 3, rr = lane & 7;
    uint32_t a_addr[2][2], w_addr[4][2];
#pragma unroll
    for (int mt = 0; mt < 2; mt++)
#pragma unroll
        for (int ks = 0; ks < 2; ks++) {
            const int row = mrow0 + mt * 16 + (jj & 1) * 8 + rr;
            const int col = ks * 8 + (jj >> 1) * 4;
            a_addr[mt][ks] = sb + (uint32_t)(O_AHI + swz(row, col)) * 4;
        }
#pragma unroll
    for (int p = 0; p < 4; p++)
#pragma unroll
        for (int ks = 0; ks < 2; ks++) {
            const int row = ncol0 + p * 16 + (jj >> 1) * 8 + rr;
            const int col = ks * 8 + (jj & 1) * 4;
            w_addr[p][ks] = sb + (uint32_t)(O_WHI0 + swz(row, col)) * 4;
        }

    // W cp.async indices: 512 (row,seg) pairs over 256 threads x2
    const int wrow0 = tid >> 2;
    const int wrow1 = (tid + 256) >> 2;
    const int wseg = tid & 3;
    const uint32_t wdst0 = (uint32_t)swz(wrow0, wseg * 4) * 4;
    const uint32_t wdst1 = (uint32_t)swz(wrow1, wseg * 4) * 4;

    // A store addresses: each 16B block at its own swizzled block address
    const int arow = tid >> 1, ahalf = tid & 1;
    const float* aptr = enc + (size_t)(b * T + t0 + arow) * E + ahalf * 16;
    const uint32_t adst0 = (uint32_t)swz(arow, ahalf * 8);
    const uint32_t adst1 = (uint32_t)swz(arow, ahalf * 8 + 4);

    float acc[2][8][4];
#pragma unroll
    for (int mt = 0; mt < 2; mt++)
#pragma unroll
        for (int nt = 0; nt < 8; nt++)
#pragma unroll
            for (int j = 0; j < 4; j++) acc[mt][nt][j] = 0.f;

    // ---- prologue: W chunk 0 -> buf0 ----
    {
        const uint32_t whi = sb + O_WHI0 * 4, wlo = sb + O_WLO0 * 4;
        cp_async16(whi + wdst0, g_wbf_hi + (size_t)wrow0 * E + wseg * 8);
        cp_async16(whi + wdst1, g_wbf_hi + (size_t)wrow1 * E + wseg * 8);
        cp_async16(wlo + wdst0, g_wbf_lo + (size_t)wrow0 * E + wseg * 8);
        cp_async16(wlo + wdst1, g_wbf_lo + (size_t)wrow1 * E + wseg * 8);
        cp_commit();
    }

    for (int c = 0; c < 16; c++) {
        const int buf = c & 1;
        const uint32_t woff = (uint32_t)buf * W_BUF_BYTES;

        // A(c) f32 loads issued BEFORE the sync: latency overlaps barrier+cp issue
        const float* ap = aptr + c * KC;
        float4 f0 = *(const float4*)(ap);
        float4 f1 = *(const float4*)(ap + 4);
        float4 f2 = *(const float4*)(ap + 8);
        float4 f3 = *(const float4*)(ap + 12);

        __syncthreads();   // MMA(c-1) done: A smem + W buf^1 free

        // issue W(c+1) into buf^1 (in flight across convert + MMA(c))
        if (c < 15) {
            const uint32_t nwoff = (uint32_t)(buf ^ 1) * W_BUF_BYTES;
            const uint32_t whi = sb + O_WHI0 * 4 + nwoff;
            const uint32_t wlo = sb + O_WLO0 * 4 + nwoff;
            const size_t go = (size_t)(c + 1) * KC;
            cp_async16(whi + wdst0, g_wbf_hi + (size_t)wrow0 * E + go + wseg * 8);
            cp_async16(whi + wdst1, g_wbf_hi + (size_t)wrow1 * E + go + wseg * 8);
            cp_async16(wlo + wdst0, g_wbf_lo + (size_t)wrow0 * E + go + wseg * 8);
            cp_async16(wlo + wdst1, g_wbf_lo + (size_t)wrow1 * E + go + wseg * 8);
            cp_commit();
        }

        // convert A(c) -> smem
        uint32_t h0, h1, h2, h3, h4, h5, h6, h7;
        uint32_t l0, l1, l2, l3, l4, l5, l6, l7;
        split2(f0.x, f0.y, h0, l0); split2(f0.z, f0.w, h1, l1);
        split2(f1.x, f1.y, h2, l2); split2(f1.z, f1.w, h3, l3);
        split2(f2.x, f2.y, h4, l4); split2(f2.z, f2.w, h5, l5);
        split2(f3.x, f3.y, h6, l6); split2(f3.z, f3.w, h7, l7);
        *(uint4*)&sm[O_AHI + adst0] = make_uint4(h0, h1, h2, h3);
        *(uint4*)&sm[O_AHI + adst1] = make_uint4(h4, h5, h6, h7);
        *(uint4*)&sm[O_ALO + adst0] = make_uint4(l0, l1, l2, l3);
        *(uint4*)&sm[O_ALO + adst1] = make_uint4(l4, l5, l6, l7);

        // W(c) arrived (issued one full iteration ago); W(c+1) still in flight
        if (c < 15) cp_wait1(); else cp_wait0();
        __syncthreads();

        // --- compute: fragments via ldmatrix.x4 ---
#pragma unroll
        for (int ks = 0; ks < 2; ks++) {
            uint32_t ah[2][4], al[2][4];
            ldsm_x4(ah[0], a_addr[0][ks]);
            ldsm_x4(ah[1], a_addr[1][ks]);
            ldsm_x4(al[0], a_addr[0][ks] + A_LO_BYTES);
            ldsm_x4(al[1], a_addr[1][ks] + A_LO_BYTES);
#pragma unroll
            for (int p = 0; p < 4; p++) {
                uint32_t wh[4], wl[4];
                ldsm_x4(wh, w_addr[p][ks] + woff);
                ldsm_x4(wl, w_addr[p][ks] + woff + W_LO_BYTES);
#pragma unroll
                for (int mt = 0; mt < 2; mt++) {
                    mma_bf16(acc[mt][2 * p], ah[mt], wh[0], wh[1]);
                    mma_bf16(acc[mt][2 * p], al[mt], wh[0], wh[1]);
                    mma_bf16(acc[mt][2 * p], ah[mt], wl[0], wl[1]);
                    mma_bf16(acc[mt][2 * p + 1], ah[mt], wh[2], wh[3]);
                    mma_bf16(acc[mt][2 * p + 1], al[mt], wh[2], wh[3]);
                    mma_bf16(acc[mt][2 * p + 1], ah[mt], wl[2], wl[3]);
                }
            }
        }
    }

    // ---- epilogue: tanh + dot(w_w), reduce over h ----
    float sums[2][2] = {{0.f, 0.f}, {0.f, 0.f}};
#pragma unroll
    for (int mt = 0; mt < 2; mt++)
#pragma unroll
        for (int nt = 0; nt < 8; nt++) {
            const int hh = ncol0 + nt * 8 + 2 * tig;
            float dv0 = __ldg(&g_dec[b * H + hh]);
            float dv1 = __ldg(&g_dec[b * H + hh + 1]);
            float wv0 = __ldg(&ww[hh]);
            float wv1 = __ldg(&ww[hh + 1]);
            sums[mt][0] += tanhf(acc[mt][nt][0] + dv0) * wv0
                         + tanhf(acc[mt][nt][1] + dv1) * wv1;
            sums[mt][1] += tanhf(acc[mt][nt][2] + dv0) * wv0
                         + tanhf(acc[mt][nt][3] + dv1) * wv1;
        }
#pragma unroll
    for (int off = 1; off <= 2; off <<= 1) {
#pragma unroll
        for (int mt = 0; mt < 2; mt++) {
            sums[mt][0] += __shfl_xor_sync(0xffffffffu, sums[mt][0], off);
            sums[mt][1] += __shfl_xor_sync(0xffffffffu, sums[mt][1], off);
        }
    }
    __syncthreads();                       // tiles dead; alias A tile as s_erg
    float* s_erg = (float*)sm;
    if (w < 4 && tig == 0) {
#pragma unroll
        for (int mt = 0; mt < 2; mt++) {
            s_erg[mrow0 + mt * 16 + g] = sums[mt][0];
            s_erg[mrow0 + mt * 16 + 8 + g] = sums[mt][1];
        }
    }
    __syncthreads();
    if (w >= 4 && tig == 0) {
#pragma unroll
        for (int mt = 0; mt < 2; mt++) {
            s_erg[mrow0 + mt * 16 + g] += sums[mt][0];
            s_erg[mrow0 + mt * 16 + 8 + g] += sums[mt][1];
        }
    }
    __syncthreads();
    if (tid < 128)
        g_erg[b * T + t0 + tid] = s_erg[tid] + wbp[0];
}

// ===========================================================================
// k_softmax
// ===========================================================================
__global__ __launch_bounds__(256)
void k_softmax(const int* __restrict__ lens, float* __restrict__ wout) {
    const int b = blockIdx.x;
    const int len = lens[b];
    const int tid = threadIdx.x;
    const int lane = tid & 31, wid = tid >> 5;
    __shared__ float sh[8];

    float m = -INFINITY;
#pragma unroll
    for (int k = 0; k < T / 256; k++) {
        int t = tid + k * 256;
        if (t < len) m = fmaxf(m, g_erg[b * T + t]);
    }
#pragma unroll
    for (int o = 16; o; o >>= 1) m = fmaxf(m, __shfl_xor_sync(0xffffffffu, m, o));
    if (lane == 0) sh[wid] = m;
    __syncthreads();
    m = (lane < 8) ? sh[lane] : -INFINITY;
#pragma unroll
    for (int o = 4; o; o >>= 1) m = fmaxf(m, __shfl_xor_sync(0xffffffffu, m, o));
    if (tid == 0) sh[0] = m;
    __syncthreads();
    m = sh[0];
    __syncthreads();

    float v[T / 256];
    float sum = 0.f;
#pragma unroll
    for (int k = 0; k < T / 256; k++) {
        int t = tid + k * 256;
        v[k] = (t < len) ? expf(g_erg[b * T + t] - m) : 0.f;
        sum += v[k];
    }
#pragma unroll
    for (int o = 16; o; o >>= 1) sum += __shfl_xor_sync(0xffffffffu, sum, o);
    if (lane == 0) sh[wid] = sum;
    __syncthreads();
    sum = (lane < 8) ? sh[lane] : 0.f;
#pragma unroll
    for (int o = 4; o; o >>= 1) sum += __shfl_xor_sync(0xffffffffu, sum, o);
    if (tid == 0) sh[0] = sum;
    __syncthreads();
    const float inv = 1.f / sh[0];

#pragma unroll
    for (int k = 0; k < T / 256; k++) {
        int t = tid + k * 256;
        wout[b * T + t] = v[k] * inv;
    }
}

// ===========================================================================
// context pass
// ===========================================================================
__global__ __launch_bounds__(512, 2)
void k_ctx_part(const float* __restrict__ enc, const float* __restrict__ wgt) {
    const int b = blockIdx.x, ts = blockIdx.y;
    const int tid = threadIdx.x;
    const int ex = tid & 127, ty = tid >> 7;
    __shared__ float sw[T / TS];
    __shared__ float4 red[4][128];
    const int t0 = ts * (T / TS);
    if (tid < T / TS) sw[tid] = wgt[b * T + t0 + tid];
    __syncthreads();

    float4 a = make_float4(0.f, 0.f, 0.f, 0.f);
    const float4* p = (const float4*)(enc + ((size_t)b * T + t0) * E) + ex;
#pragma unroll
    for (int t = ty; t < T / TS; t += 4) {
        float wv = sw[t];
        float4 v = p[(size_t)t * (E / 4)];
        a.x = fmaf(wv, v.x, a.x);
        a.y = fmaf(wv, v.y, a.y);
        a.z = fmaf(wv, v.z, a.z);
        a.w = fmaf(wv, v.w, a.w);
    }
    red[ty][ex] = a;
    __syncthreads();
    if (ty == 0) {
        float4 r1 = red[1][ex], r2 = red[2][ex], r3 = red[3][ex];
        a.x += r1.x + r2.x + r3.x;
        a.y += r1.y + r2.y + r3.y;
        a.z += r1.z + r2.z + r3.z;
        a.w += r1.w + r2.w + r3.w;
        *(float4*)&g_ctx_part[ts][b][ex * 4] = a;
    }
}

__global__ __launch_bounds__(512)
void k_ctx_reduce(float* __restrict__ ctx) {
    const int b = blockIdx.x;
    const int e = threadIdx.x;
    float s = 0.f;
#pragma unroll
    for (int k = 0; k < TS; k++) s += g_ctx_part[k][b][e];
    ctx[b * E + e] = s;
}

// ===========================================================================
extern "C" void kernel_launch(void* const* d_in, const int* in_sizes, int n_in,
                              void* d_out, int out_size) {
    const float* enc  = (const float*)d_in[0];
    const int*   lens = (const int*)  d_in[1];
    const float* ds   = (const float*)d_in[2];
    const float* Wenc = (const float*)d_in[4];
    const float* benc = (const float*)d_in[5];
    const float* Wdec = (const float*)d_in[6];
    const float* ww   = (const float*)d_in[7];
    const float* wb   = (const float*)d_in[8];

    float* ctx = (float*)d_out;           // [B,E]
    float* wgt = (float*)d_out + B * E;   // [B,T]

    k_wprep<<<dim3(E / 32, H / 32), dim3(32, 32)>>>(Wenc);   // idx 0
    k_dec<<<B, dim3(128, 8)>>>(ds, Wdec, benc);              // idx 1
    k_probe<<<1, 32>>>();                                    // idx 2
    k_erg<<<B * 16, 256>>>(enc, ww, wb);                     // idx 3 <- profiled
    k_softmax<<<B, 256>>>(lens, wgt);                        // idx 4
    k_ctx_part<<<dim3(B, TS), 512>>>(enc, wgt);              // idx 5
    k_ctx_reduce<<<B, E>>>(ctx);                             // idx 6
}

// round 10
// speedup vs baseline: 1.5959x; 1.1415x over previous
#include <cuda_runtime.h>
#include <cuda_fp16.h>
#include <math.h>
#include <stdint.h>

#define B 32
#define T 2048
#define E 512
#define D 1024
#define H 128

#define TS 32      // t-splits in context pass
#define KC 32      // k-chunk (e) per stage in k_erg

// ---- scratch ----
__device__ float g_dec[B * H];
__device__ float g_erg[B * T];
__device__ float g_ctx_part[TS][B][E];
__device__ __half g_wh_hi[H * E];   // W_enc^T fp16 hi: [h][e]
__device__ __half g_wh_lo[H * E];   // fp16 residual

// ===========================================================================
// helpers
// ===========================================================================
__device__ __forceinline__ uint32_t smem_u32(const void* p) {
    uint32_t a;
    asm("{ .reg .u64 t; cvta.to.shared.u64 t, %1; cvt.u32.u64 %0, t; }"
        : "=r"(a) : "l"(p));
    return a;
}
__device__ __forceinline__ void cp_async16(uint32_t dst, const void* src) {
    asm volatile("cp.async.ca.shared.global [%0], [%1], 16;"
                 :: "r"(dst), "l"(src) : "memory");
}
__device__ __forceinline__ void cp_commit() {
    asm volatile("cp.async.commit_group;" ::: "memory");
}
__device__ __forceinline__ void cp_wait1() {
    asm volatile("cp.async.wait_group 1;" ::: "memory");
}
__device__ __forceinline__ void cp_wait0() {
    asm volatile("cp.async.wait_group 0;" ::: "memory");
}
// pack two f32 -> f16x2 (x -> low half)
__device__ __forceinline__ uint32_t pack_h2(float x, float y) {
    uint32_t r;
    asm("cvt.rn.f16x2.f32 %0, %1, %2;" : "=r"(r) : "f"(y), "f"(x));
    return r;
}
__device__ __forceinline__ void mma_f16(float* c, const uint32_t* a,
                                        uint32_t b0, uint32_t b1) {
    asm volatile(
        "mma.sync.aligned.m16n8k16.row.col.f32.f16.f16.f32 "
        "{%0,%1,%2,%3}, {%4,%5,%6,%7}, {%8,%9}, {%0,%1,%2,%3};"
        : "+f"(c[0]), "+f"(c[1]), "+f"(c[2]), "+f"(c[3])
        : "r"(a[0]), "r"(a[1]), "r"(a[2]), "r"(a[3]), "r"(b0), "r"(b1));
}
__device__ __forceinline__ void ldsm_x4(uint32_t* r, uint32_t addr) {
    asm volatile("ldmatrix.sync.aligned.m8n8.x4.shared.b16 {%0,%1,%2,%3}, [%4];"
                 : "=r"(r[0]), "=r"(r[1]), "=r"(r[2]), "=r"(r[3]) : "r"(addr));
}
// packed tile: row stride 16 u32; XOR-swizzle 4-u32 blocks (conflict-free,
// enumerated for uint4 stores, cp.async 16B stores, all ldmatrix phases)
__device__ __forceinline__ int swz(int row, int col) {
    return row * 16 + (col ^ (((row >> 1) & 3) << 2));
}

// ===========================================================================
// k_wprep: W_enc [E][H] -> fp16 hi/lo transposed [H][E]
// ===========================================================================
__global__ void k_wprep(const float* __restrict__ W) {
    __shared__ float tile[32][33];
    const int e0 = blockIdx.x * 32, h0 = blockIdx.y * 32;
    const int tx = threadIdx.x, ty = threadIdx.y;
    tile[ty][tx] = W[(size_t)(e0 + ty) * H + h0 + tx];
    __syncthreads();
    float v = tile[tx][ty];
    __half hb = __float2half_rn(v);
    float lo = v - __half2float(hb);
    g_wh_hi[(size_t)(h0 + ty) * E + e0 + tx] = hb;
    g_wh_lo[(size_t)(h0 + ty) * E + e0 + tx] = __float2half_rn(lo);
}

// ===========================================================================
// k_dec
// ===========================================================================
__global__ __launch_bounds__(1024)
void k_dec(const float* __restrict__ ds, const float* __restrict__ Wdec,
           const float* __restrict__ benc) {
    __shared__ float s[8][128];
    const int b = blockIdx.x;
    const int h = threadIdx.x, ty = threadIdx.y;
    float acc = 0.f;
    const float* dsr = ds + b * D + ty * 128;
    const float* wp = Wdec + (size_t)(ty * 128) * H + h;
#pragma unroll 8
    for (int d = 0; d < 128; d++)
        acc = fmaf(dsr[d], wp[(size_t)d * H], acc);
    s[ty][h] = acc;
    __syncthreads();
    if (ty == 0) {
        float t = benc[h];
#pragma unroll
        for (int k = 0; k < 8; k++) t += s[k][h];
        g_dec[b * H + h] = t;
    }
}

// ===========================================================================
// k_probe: slot filler so k_erg stays at profiled launch index 3
// ===========================================================================
__global__ void k_probe() { }

// ===========================================================================
// k_erg: fp16 2-term GEMM (A single fp16, W = hi+lo fp16), ldmatrix, W dbuf
// grid 512, block 256 (8 warps; warp = 32t x 64h); 40KB static smem
// ===========================================================================
#define TILE16 (128 * 16)             // 2048 u32 = 8 KB per packed tile
#define O_A    0
#define O_WHI0 TILE16                 // W hi bufs at TILE16, 2*TILE16
#define O_WLO0 (3 * TILE16)           // W lo bufs at 3*TILE16, 4*TILE16
#define W_LO_BYTES (2 * TILE16 * 4)   // W hi -> lo: 16384 B (both bufs)
#define W_BUF_BYTES (TILE16 * 4)      // buf0 -> buf1: 8192 B

__global__ __launch_bounds__(256, 2)
void k_erg(const float* __restrict__ enc, const float* __restrict__ ww,
           const float* __restrict__ wbp) {
    __shared__ uint32_t sm[5 * TILE16];        // 40960 B

    const int tid = threadIdx.x;
    const int w = tid >> 5, lane = tid & 31;
    const int g = lane >> 2, tig = lane & 3;
    const int b = blockIdx.x >> 4;
    const int t0 = (blockIdx.x & 15) * 128;
    const int mrow0 = (w & 3) * 32;
    const int ncol0 = (w >> 2) * 64;

    const uint32_t sb = smem_u32(sm);

    // ---- loop-invariant ldmatrix addresses (XOR swizzle folded in) ----
    const int jj = lane >> 3, rr = lane & 7;
    uint32_t a_addr[2][2], w_addr[4][2];
#pragma unroll
    for (int mt = 0; mt < 2; mt++)
#pragma unroll
        for (int ks = 0; ks < 2; ks++) {
            const int row = mrow0 + mt * 16 + (jj & 1) * 8 + rr;
            const int col = ks * 8 + (jj >> 1) * 4;
            a_addr[mt][ks] = sb + (uint32_t)(O_A + swz(row, col)) * 4;
        }
#pragma unroll
    for (int p = 0; p < 4; p++)
#pragma unroll
        for (int ks = 0; ks < 2; ks++) {
            const int row = ncol0 + p * 16 + (jj >> 1) * 8 + rr;
            const int col = ks * 8 + (jj & 1) * 4;
            w_addr[p][ks] = sb + (uint32_t)(O_WHI0 + swz(row, col)) * 4;
        }

    // W cp.async: 512 (row,seg) pairs over 256 threads x2
    const int wrow0 = tid >> 2;
    const int wrow1 = (tid + 256) >> 2;
    const int wseg = tid & 3;
    const uint32_t wdst0 = (uint32_t)swz(wrow0, wseg * 4) * 4;
    const uint32_t wdst1 = (uint32_t)swz(wrow1, wseg * 4) * 4;

    // A store addresses: each 16B block at its own swizzled block address
    const int arow = tid >> 1, ahalf = tid & 1;
    const float* aptr = enc + (size_t)(b * T + t0 + arow) * E + ahalf * 16;
    const uint32_t adst0 = (uint32_t)swz(arow, ahalf * 8);
    const uint32_t adst1 = (uint32_t)swz(arow, ahalf * 8 + 4);

    float acc[2][8][4];
#pragma unroll
    for (int mt = 0; mt < 2; mt++)
#pragma unroll
        for (int nt = 0; nt < 8; nt++)
#pragma unroll
            for (int j = 0; j < 4; j++) acc[mt][nt][j] = 0.f;

    // ---- prologue: W chunk 0 -> buf0 ----
    {
        const uint32_t whi = sb + O_WHI0 * 4, wlo = sb + O_WLO0 * 4;
        cp_async16(whi + wdst0, g_wh_hi + (size_t)wrow0 * E + wseg * 8);
        cp_async16(whi + wdst1, g_wh_hi + (size_t)wrow1 * E + wseg * 8);
        cp_async16(wlo + wdst0, g_wh_lo + (size_t)wrow0 * E + wseg * 8);
        cp_async16(wlo + wdst1, g_wh_lo + (size_t)wrow1 * E + wseg * 8);
        cp_commit();
    }

    for (int c = 0; c < 16; c++) {
        const int buf = c & 1;
        const uint32_t woff = (uint32_t)buf * W_BUF_BYTES;

        // A(c) f32 loads issued BEFORE the sync: latency overlaps barrier+cp
        const float* ap = aptr + c * KC;
        float4 f0 = *(const float4*)(ap);
        float4 f1 = *(const float4*)(ap + 4);
        float4 f2 = *(const float4*)(ap + 8);
        float4 f3 = *(const float4*)(ap + 12);

        __syncthreads();   // MMA(c-1) done: A smem + W buf^1 free

        // issue W(c+1) into buf^1 (in flight across convert + MMA(c))
        if (c < 15) {
            const uint32_t nwoff = (uint32_t)(buf ^ 1) * W_BUF_BYTES;
            const uint32_t whi = sb + O_WHI0 * 4 + nwoff;
            const uint32_t wlo = sb + O_WLO0 * 4 + nwoff;
            const size_t go = (size_t)(c + 1) * KC;
            cp_async16(whi + wdst0, g_wh_hi + (size_t)wrow0 * E + go + wseg * 8);
            cp_async16(whi + wdst1, g_wh_hi + (size_t)wrow1 * E + go + wseg * 8);
            cp_async16(wlo + wdst0, g_wh_lo + (size_t)wrow0 * E + go + wseg * 8);
            cp_async16(wlo + wdst1, g_wh_lo + (size_t)wrow1 * E + go + wseg * 8);
            cp_commit();
        }

        // convert A(c) -> fp16 smem (single tile, no residual)
        *(uint4*)&sm[O_A + adst0] = make_uint4(
            pack_h2(f0.x, f0.y), pack_h2(f0.z, f0.w),
            pack_h2(f1.x, f1.y), pack_h2(f1.z, f1.w));
        *(uint4*)&sm[O_A + adst1] = make_uint4(
            pack_h2(f2.x, f2.y), pack_h2(f2.z, f2.w),
            pack_h2(f3.x, f3.y), pack_h2(f3.z, f3.w));

        // W(c) arrived (issued one full iteration ago); W(c+1) still in flight
        if (c < 15) cp_wait1(); else cp_wait0();
        __syncthreads();

        // --- compute: fragments via ldmatrix.x4; 2 products per acc tile ---
#pragma unroll
        for (int ks = 0; ks < 2; ks++) {
            uint32_t ah[2][4];
            ldsm_x4(ah[0], a_addr[0][ks]);
            ldsm_x4(ah[1], a_addr[1][ks]);
#pragma unroll
            for (int p = 0; p < 4; p++) {
                uint32_t wh[4], wl[4];
                ldsm_x4(wh, w_addr[p][ks] + woff);
                ldsm_x4(wl, w_addr[p][ks] + woff + W_LO_BYTES);
#pragma unroll
                for (int mt = 0; mt < 2; mt++) {
                    mma_f16(acc[mt][2 * p], ah[mt], wh[0], wh[1]);
                    mma_f16(acc[mt][2 * p], ah[mt], wl[0], wl[1]);
                    mma_f16(acc[mt][2 * p + 1], ah[mt], wh[2], wh[3]);
                    mma_f16(acc[mt][2 * p + 1], ah[mt], wl[2], wl[3]);
                }
            }
        }
    }

    // ---- epilogue: tanh + dot(w_w), reduce over h ----
    float sums[2][2] = {{0.f, 0.f}, {0.f, 0.f}};
#pragma unroll
    for (int mt = 0; mt < 2; mt++)
#pragma unroll
        for (int nt = 0; nt < 8; nt++) {
            const int hh = ncol0 + nt * 8 + 2 * tig;
            float dv0 = __ldg(&g_dec[b * H + hh]);
            float dv1 = __ldg(&g_dec[b * H + hh + 1]);
            float wv0 = __ldg(&ww[hh]);
            float wv1 = __ldg(&ww[hh + 1]);
            sums[mt][0] += tanhf(acc[mt][nt][0] + dv0) * wv0
                         + tanhf(acc[mt][nt][1] + dv1) * wv1;
            sums[mt][1] += tanhf(acc[mt][nt][2] + dv0) * wv0
                         + tanhf(acc[mt][nt][3] + dv1) * wv1;
        }
#pragma unroll
    for (int off = 1; off <= 2; off <<= 1) {
#pragma unroll
        for (int mt = 0; mt < 2; mt++) {
            sums[mt][0] += __shfl_xor_sync(0xffffffffu, sums[mt][0], off);
            sums[mt][1] += __shfl_xor_sync(0xffffffffu, sums[mt][1], off);
        }
    }
    __syncthreads();                       // tiles dead; alias A tile as s_erg
    float* s_erg = (float*)sm;
    if (w < 4 && tig == 0) {
#pragma unroll
        for (int mt = 0; mt < 2; mt++) {
            s_erg[mrow0 + mt * 16 + g] = sums[mt][0];
            s_erg[mrow0 + mt * 16 + 8 + g] = sums[mt][1];
        }
    }
    __syncthreads();
    if (w >= 4 && tig == 0) {
#pragma unroll
        for (int mt = 0; mt < 2; mt++) {
            s_erg[mrow0 + mt * 16 + g] += sums[mt][0];
            s_erg[mrow0 + mt * 16 + 8 + g] += sums[mt][1];
        }
    }
    __syncthreads();
    if (tid < 128)
        g_erg[b * T + t0 + tid] = s_erg[tid] + wbp[0];
}

// ===========================================================================
// k_softmax
// ===========================================================================
__global__ __launch_bounds__(256)
void k_softmax(const int* __restrict__ lens, float* __restrict__ wout) {
    const int b = blockIdx.x;
    const int len = lens[b];
    const int tid = threadIdx.x;
    const int lane = tid & 31, wid = tid >> 5;
    __shared__ float sh[8];

    float m = -INFINITY;
#pragma unroll
    for (int k = 0; k < T / 256; k++) {
        int t = tid + k * 256;
        if (t < len) m = fmaxf(m, g_erg[b * T + t]);
    }
#pragma unroll
    for (int o = 16; o; o >>= 1) m = fmaxf(m, __shfl_xor_sync(0xffffffffu, m, o));
    if (lane == 0) sh[wid] = m;
    __syncthreads();
    m = (lane < 8) ? sh[lane] : -INFINITY;
#pragma unroll
    for (int o = 4; o; o >>= 1) m = fmaxf(m, __shfl_xor_sync(0xffffffffu, m, o));
    if (tid == 0) sh[0] = m;
    __syncthreads();
    m = sh[0];
    __syncthreads();

    float v[T / 256];
    float sum = 0.f;
#pragma unroll
    for (int k = 0; k < T / 256; k++) {
        int t = tid + k * 256;
        v[k] = (t < len) ? expf(g_erg[b * T + t] - m) : 0.f;
        sum += v[k];
    }
#pragma unroll
    for (int o = 16; o; o >>= 1) sum += __shfl_xor_sync(0xffffffffu, sum, o);
    if (lane == 0) sh[wid] = sum;
    __syncthreads();
    sum = (lane < 8) ? sh[lane] : 0.f;
#pragma unroll
    for (int o = 4; o; o >>= 1) sum += __shfl_xor_sync(0xffffffffu, sum, o);
    if (tid == 0) sh[0] = sum;
    __syncthreads();
    const float inv = 1.f / sh[0];

#pragma unroll
    for (int k = 0; k < T / 256; k++) {
        int t = tid + k * 256;
        wout[b * T + t] = v[k] * inv;
    }
}

// ===========================================================================
// context pass
// ===========================================================================
__global__ __launch_bounds__(512, 2)
void k_ctx_part(const float* __restrict__ enc, const float* __restrict__ wgt) {
    const int b = blockIdx.x, ts = blockIdx.y;
    const int tid = threadIdx.x;
    const int ex = tid & 127, ty = tid >> 7;
    __shared__ float sw[T / TS];
    __shared__ float4 red[4][128];
    const int t0 = ts * (T / TS);
    if (tid < T / TS) sw[tid] = wgt[b * T + t0 + tid];
    __syncthreads();

    float4 a = make_float4(0.f, 0.f, 0.f, 0.f);
    const float4* p = (const float4*)(enc + ((size_t)b * T + t0) * E) + ex;
#pragma unroll
    for (int t = ty; t < T / TS; t += 4) {
        float wv = sw[t];
        float4 v = p[(size_t)t * (E / 4)];
        a.x = fmaf(wv, v.x, a.x);
        a.y = fmaf(wv, v.y, a.y);
        a.z = fmaf(wv, v.z, a.z);
        a.w = fmaf(wv, v.w, a.w);
    }
    red[ty][ex] = a;
    __syncthreads();
    if (ty == 0) {
        float4 r1 = red[1][ex], r2 = red[2][ex], r3 = red[3][ex];
        a.x += r1.x + r2.x + r3.x;
        a.y += r1.y + r2.y + r3.y;
        a.z += r1.z + r2.z + r3.z;
        a.w += r1.w + r2.w + r3.w;
        *(float4*)&g_ctx_part[ts][b][ex * 4] = a;
    }
}

__global__ __launch_bounds__(512)
void k_ctx_reduce(float* __restrict__ ctx) {
    const int b = blockIdx.x;
    const int e = threadIdx.x;
    float s = 0.f;
#pragma unroll
    for (int k = 0; k < TS; k++) s += g_ctx_part[k][b][e];
    ctx[b * E + e] = s;
}

// ===========================================================================
extern "C" void kernel_launch(void* const* d_in, const int* in_sizes, int n_in,
                              void* d_out, int out_size) {
    const float* enc  = (const float*)d_in[0];
    const int*   lens = (const int*)  d_in[1];
    const float* ds   = (const float*)d_in[2];
    const float* Wenc = (const float*)d_in[4];
    const float* benc = (const float*)d_in[5];
    const float* Wdec = (const float*)d_in[6];
    const float* ww   = (const float*)d_in[7];
    const float* wb   = (const float*)d_in[8];

    float* ctx = (float*)d_out;           // [B,E]
    float* wgt = (float*)d_out + B * E;   // [B,T]

    k_wprep<<<dim3(E / 32, H / 32), dim3(32, 32)>>>(Wenc);   // idx 0
    k_dec<<<B, dim3(128, 8)>>>(ds, Wdec, benc);              // idx 1
    k_probe<<<1, 32>>>();                                    // idx 2
    k_erg<<<B * 16, 256>>>(enc, ww, wb);                     // idx 3 <- profiled
    k_softmax<<<B, 256>>>(lens, wgt);                        // idx 4
    k_ctx_part<<<dim3(B, TS), 512>>>(enc, wgt);              // idx 5
    k_ctx_reduce<<<B, E>>>(ctx);                             // idx 6
}

// round 12
// speedup vs baseline: 1.9036x; 1.1928x over previous
#include <cuda_runtime.h>
#include <cuda_fp16.h>
#include <math.h>
#include <stdint.h>

#define B 32
#define T 2048
#define E 512
#define D 1024
#define H 128

#define TS 32      // t-splits in context pass
#define KC 32      // k-chunk (e) per stage in k_erg

// ---- scratch ----
__device__ float g_dec[B * H];
__device__ float g_erg[B * T];
__device__ float g_ctx_part[TS][B][E];
__device__ __half g_wh[H * E];      // W_enc^T fp16: [h][e]

// ===========================================================================
// helpers
// ===========================================================================
__device__ __forceinline__ uint32_t smem_u32(const void* p) {
    uint32_t a;
    asm("{ .reg .u64 t; cvta.to.shared.u64 t, %1; cvt.u32.u64 %0, t; }"
        : "=r"(a) : "l"(p));
    return a;
}
__device__ __forceinline__ void cp_async16(uint32_t dst, const void* src) {
    asm volatile("cp.async.ca.shared.global [%0], [%1], 16;"
                 :: "r"(dst), "l"(src) : "memory");
}
__device__ __forceinline__ void cp_commit() {
    asm volatile("cp.async.commit_group;" ::: "memory");
}
__device__ __forceinline__ void cp_wait1() {
    asm volatile("cp.async.wait_group 1;" ::: "memory");
}
__device__ __forceinline__ void cp_wait0() {
    asm volatile("cp.async.wait_group 0;" ::: "memory");
}
// pack two f32 -> f16x2 (x -> low half)
__device__ __forceinline__ uint32_t pack_h2(float x, float y) {
    uint32_t r;
    asm("cvt.rn.f16x2.f32 %0, %1, %2;" : "=r"(r) : "f"(y), "f"(x));
    return r;
}
__device__ __forceinline__ void mma_f16(float* c, const uint32_t* a,
                                        uint32_t b0, uint32_t b1) {
    asm volatile(
        "mma.sync.aligned.m16n8k16.row.col.f32.f16.f16.f32 "
        "{%0,%1,%2,%3}, {%4,%5,%6,%7}, {%8,%9}, {%0,%1,%2,%3};"
        : "+f"(c[0]), "+f"(c[1]), "+f"(c[2]), "+f"(c[3])
        : "r"(a[0]), "r"(a[1]), "r"(a[2]), "r"(a[3]), "r"(b0), "r"(b1));
}
__device__ __forceinline__ void ldsm_x4(uint32_t* r, uint32_t addr) {
    asm volatile("ldmatrix.sync.aligned.m8n8.x4.shared.b16 {%0,%1,%2,%3}, [%4];"
                 : "=r"(r[0]), "=r"(r[1]), "=r"(r[2]), "=r"(r[3]) : "r"(addr));
}
// packed tile: row stride 16 u32; XOR-swizzle 4-u32 blocks (conflict-free,
// enumerated for uint4 stores, cp.async 16B stores, all ldmatrix phases)
__device__ __forceinline__ int swz(int row, int col) {
    return row * 16 + (col ^ (((row >> 1) & 3) << 2));
}

// ===========================================================================
// k_wprep: W_enc [E][H] -> fp16 transposed [H][E]
// ===========================================================================
__global__ void k_wprep(const float* __restrict__ W) {
    __shared__ float tile[32][33];
    const int e0 = blockIdx.x * 32, h0 = blockIdx.y * 32;
    const int tx = threadIdx.x, ty = threadIdx.y;
    tile[ty][tx] = W[(size_t)(e0 + ty) * H + h0 + tx];
    __syncthreads();
    g_wh[(size_t)(h0 + ty) * E + e0 + tx] = __float2half_rn(tile[tx][ty]);
}

// ===========================================================================
// k_dec
// ===========================================================================
__global__ __launch_bounds__(1024)
void k_dec(const float* __restrict__ ds, const float* __restrict__ Wdec,
           const float* __restrict__ benc) {
    __shared__ float s[8][128];
    const int b = blockIdx.x;
    const int h = threadIdx.x, ty = threadIdx.y;
    float acc = 0.f;
    const float* dsr = ds + b * D + ty * 128;
    const float* wp = Wdec + (size_t)(ty * 128) * H + h;
#pragma unroll 8
    for (int d = 0; d < 128; d++)
        acc = fmaf(dsr[d], wp[(size_t)d * H], acc);
    s[ty][h] = acc;
    __syncthreads();
    if (ty == 0) {
        float t = benc[h];
#pragma unroll
        for (int k = 0; k < 8; k++) t += s[k][h];
        g_dec[b * H + h] = t;
    }
}

// ===========================================================================
// k_probe: slot filler so k_erg stays at profiled launch index 3
// ===========================================================================
__global__ void k_probe() { }

// ===========================================================================
// k_erg: fp16 single-product GEMM (A fp16, W fp16), ldmatrix, W double-buffer
// grid 512, block 256 (8 warps; warp = 32t x 64h); 24KB static smem
// ===========================================================================
#define TILE16 (128 * 16)             // 2048 u32 = 8 KB per packed tile
#define O_A    0
#define O_W0   TILE16                 // W bufs at TILE16, 2*TILE16
#define W_BUF_BYTES (TILE16 * 4)      // buf0 -> buf1: 8192 B

__global__ __launch_bounds__(256, 2)
void k_erg(const float* __restrict__ enc, const float* __restrict__ ww,
           const float* __restrict__ wbp) {
    __shared__ uint32_t sm[3 * TILE16];        // 24576 B

    const int tid = threadIdx.x;
    const int w = tid >> 5, lane = tid & 31;
    const int g = lane >> 2, tig = lane & 3;
    const int b = blockIdx.x >> 4;
    const int t0 = (blockIdx.x & 15) * 128;
    const int mrow0 = (w & 3) * 32;
    const int ncol0 = (w >> 2) * 64;

    const uint32_t sb = smem_u32(sm);

    // ---- loop-invariant ldmatrix addresses (XOR swizzle folded in) ----
    const int jj = lane >> 3, rr = lane & 7;
    uint32_t a_addr[2][2], w_addr[4][2];
#pragma unroll
    for (int mt = 0; mt < 2; mt++)
#pragma unroll
        for (int ks = 0; ks < 2; ks++) {
            const int row = mrow0 + mt * 16 + (jj & 1) * 8 + rr;
            const int col = ks * 8 + (jj >> 1) * 4;
            a_addr[mt][ks] = sb + (uint32_t)(O_A + swz(row, col)) * 4;
        }
#pragma unroll
    for (int p = 0; p < 4; p++)
#pragma unroll
        for (int ks = 0; ks < 2; ks++) {
            const int row = ncol0 + p * 16 + (jj >> 1) * 8 + rr;
            const int col = ks * 8 + (jj & 1) * 4;
            w_addr[p][ks] = sb + (uint32_t)(O_W0 + swz(row, col)) * 4;
        }

    // W cp.async: 512 (row,seg) pairs over 256 threads x2
    const int wrow0 = tid >> 2;
    const int wrow1 = (tid + 256) >> 2;
    const int wseg = tid & 3;
    const uint32_t wdst0 = (uint32_t)swz(wrow0, wseg * 4) * 4;
    const uint32_t wdst1 = (uint32_t)swz(wrow1, wseg * 4) * 4;

    // A store addresses: each 16B block at its own swizzled block address
    const int arow = tid >> 1, ahalf = tid & 1;
    const float* aptr = enc + (size_t)(b * T + t0 + arow) * E + ahalf * 16;
    const uint32_t adst0 = (uint32_t)swz(arow, ahalf * 8);
    const uint32_t adst1 = (uint32_t)swz(arow, ahalf * 8 + 4);

    float acc[2][8][4];
#pragma unroll
    for (int mt = 0; mt < 2; mt++)
#pragma unroll
        for (int nt = 0; nt < 8; nt++)
#pragma unroll
            for (int j = 0; j < 4; j++) acc[mt][nt][j] = 0.f;

    // ---- prologue: W chunk 0 -> buf0 ----
    {
        const uint32_t wb0 = sb + O_W0 * 4;
        cp_async16(wb0 + wdst0, g_wh + (size_t)wrow0 * E + wseg * 8);
        cp_async16(wb0 + wdst1, g_wh + (size_t)wrow1 * E + wseg * 8);
        cp_commit();
    }

    for (int c = 0; c < 16; c++) {
        const int buf = c & 1;
        const uint32_t woff = (uint32_t)buf * W_BUF_BYTES;

        // A(c) f32 loads issued BEFORE the sync: latency overlaps barrier+cp
        const float* ap = aptr + c * KC;
        float4 f0 = *(const float4*)(ap);
        float4 f1 = *(const float4*)(ap + 4);
        float4 f2 = *(const float4*)(ap + 8);
        float4 f3 = *(const float4*)(ap + 12);

        __syncthreads();   // MMA(c-1) done: A smem + W buf^1 free

        // issue W(c+1) into buf^1 (in flight across convert + MMA(c))
        if (c < 15) {
            const uint32_t wbn = sb + O_W0 * 4 + (uint32_t)(buf ^ 1) * W_BUF_BYTES;
            const size_t go = (size_t)(c + 1) * KC;
            cp_async16(wbn + wdst0, g_wh + (size_t)wrow0 * E + go + wseg * 8);
            cp_async16(wbn + wdst1, g_wh + (size_t)wrow1 * E + go + wseg * 8);
            cp_commit();
        }

        // convert A(c) -> fp16 smem
        *(uint4*)&sm[O_A + adst0] = make_uint4(
            pack_h2(f0.x, f0.y), pack_h2(f0.z, f0.w),
            pack_h2(f1.x, f1.y), pack_h2(f1.z, f1.w));
        *(uint4*)&sm[O_A + adst1] = make_uint4(
            pack_h2(f2.x, f2.y), pack_h2(f2.z, f2.w),
            pack_h2(f3.x, f3.y), pack_h2(f3.z, f3.w));

        // W(c) arrived (issued one full iteration ago); W(c+1) still in flight
        if (c < 15) cp_wait1(); else cp_wait0();
        __syncthreads();

        // --- compute: fragments via ldmatrix.x4; 1 product per acc tile ---
#pragma unroll
        for (int ks = 0; ks < 2; ks++) {
            uint32_t ah[2][4];
            ldsm_x4(ah[0], a_addr[0][ks]);
            ldsm_x4(ah[1], a_addr[1][ks]);
#pragma unroll
            for (int p = 0; p < 4; p++) {
                uint32_t wh[4];
                ldsm_x4(wh, w_addr[p][ks] + woff);
#pragma unroll
                for (int mt = 0; mt < 2; mt++) {
                    mma_f16(acc[mt][2 * p], ah[mt], wh[0], wh[1]);
                    mma_f16(acc[mt][2 * p + 1], ah[mt], wh[2], wh[3]);
                }
            }
        }
    }

    // ---- epilogue: tanh + dot(w_w), reduce over h ----
    float sums[2][2] = {{0.f, 0.f}, {0.f, 0.f}};
#pragma unroll
    for (int mt = 0; mt < 2; mt++)
#pragma unroll
        for (int nt = 0; nt < 8; nt++) {
            const int hh = ncol0 + nt * 8 + 2 * tig;
            float dv0 = __ldg(&g_dec[b * H + hh]);
            float dv1 = __ldg(&g_dec[b * H + hh + 1]);
            float wv0 = __ldg(&ww[hh]);
            float wv1 = __ldg(&ww[hh + 1]);
            sums[mt][0] += tanhf(acc[mt][nt][0] + dv0) * wv0
                         + tanhf(acc[mt][nt][1] + dv1) * wv1;
            sums[mt][1] += tanhf(acc[mt][nt][2] + dv0) * wv0
                         + tanhf(acc[mt][nt][3] + dv1) * wv1;
        }
#pragma unroll
    for (int off = 1; off <= 2; off <<= 1) {
#pragma unroll
        for (int mt = 0; mt < 2; mt++) {
            sums[mt][0] += __shfl_xor_sync(0xffffffffu, sums[mt][0], off);
            sums[mt][1] += __shfl_xor_sync(0xffffffffu, sums[mt][1], off);
        }
    }
    __syncthreads();                       // tiles dead; alias A tile as s_erg
    float* s_erg = (float*)sm;
    if (w < 4 && tig == 0) {
#pragma unroll
        for (int mt = 0; mt < 2; mt++) {
            s_erg[mrow0 + mt * 16 + g] = sums[mt][0];
            s_erg[mrow0 + mt * 16 + 8 + g] = sums[mt][1];
        }
    }
    __syncthreads();
    if (w >= 4 && tig == 0) {
#pragma unroll
        for (int mt = 0; mt < 2; mt++) {
            s_erg[mrow0 + mt * 16 + g] += sums[mt][0];
            s_erg[mrow0 + mt * 16 + 8 + g] += sums[mt][1];
        }
    }
    __syncthreads();
    if (tid < 128)
        g_erg[b * T + t0 + tid] = s_erg[tid] + wbp[0];
}

// ===========================================================================
// k_softmax
// ===========================================================================
__global__ __launch_bounds__(256)
void k_softmax(const int* __restrict__ lens, float* __restrict__ wout) {
    const int b = blockIdx.x;
    const int len = lens[b];
    const int tid = threadIdx.x;
    const int lane = tid & 31, wid = tid >> 5;
    __shared__ float sh[8];

    float m = -INFINITY;
#pragma unroll
    for (int k = 0; k < T / 256; k++) {
        int t = tid + k * 256;
        if (t < len) m = fmaxf(m, g_erg[b * T + t]);
    }
#pragma unroll
    for (int o = 16; o; o >>= 1) m = fmaxf(m, __shfl_xor_sync(0xffffffffu, m, o));
    if (lane == 0) sh[wid] = m;
    __syncthreads();
    m = (lane < 8) ? sh[lane] : -INFINITY;
#pragma unroll
    for (int o = 4; o; o >>= 1) m = fmaxf(m, __shfl_xor_sync(0xffffffffu, m, o));
    if (tid == 0) sh[0] = m;
    __syncthreads();
    m = sh[0];
    __syncthreads();

    float v[T / 256];
    float sum = 0.f;
#pragma unroll
    for (int k = 0; k < T / 256; k++) {
        int t = tid + k * 256;
        v[k] = (t < len) ? expf(g_erg[b * T + t] - m) : 0.f;
        sum += v[k];
    }
#pragma unroll
    for (int o = 16; o; o >>= 1) sum += __shfl_xor_sync(0xffffffffu, sum, o);
    if (lane == 0) sh[wid] = sum;
    __syncthreads();
    sum = (lane < 8) ? sh[lane] : 0.f;
#pragma unroll
    for (int o = 4; o; o >>= 1) sum += __shfl_xor_sync(0xffffffffu, sum, o);
    if (tid == 0) sh[0] = sum;
    __syncthreads();
    const float inv = 1.f / sh[0];

#pragma unroll
    for (int k = 0; k < T / 256; k++) {
        int t = tid + k * 256;
        wout[b * T + t] = v[k] * inv;
    }
}

// ===========================================================================
// context pass
// ===========================================================================
__global__ __launch_bounds__(512, 2)
void k_ctx_part(const float* __restrict__ enc, const float* __restrict__ wgt) {
    const int b = blockIdx.x, ts = blockIdx.y;
    const int tid = threadIdx.x;
    const int ex = tid & 127, ty = tid >> 7;
    __shared__ float sw[T / TS];
    __shared__ float4 red[4][128];
    const int t0 = ts * (T / TS);
    if (tid < T / TS) sw[tid] = wgt[b * T + t0 + tid];
    __syncthreads();

    float4 a = make_float4(0.f, 0.f, 0.f, 0.f);
    const float4* p = (const float4*)(enc + ((size_t)b * T + t0) * E) + ex;
#pragma unroll
    for (int t = ty; t < T / TS; t += 4) {
        float wv = sw[t];
        float4 v = p[(size_t)t * (E / 4)];
        a.x = fmaf(wv, v.x, a.x);
        a.y = fmaf(wv, v.y, a.y);
        a.z = fmaf(wv, v.z, a.z);
        a.w = fmaf(wv, v.w, a.w);
    }
    red[ty][ex] = a;
    __syncthreads();
    if (ty == 0) {
        float4 r1 = red[1][ex], r2 = red[2][ex], r3 = red[3][ex];
        a.x += r1.x + r2.x + r3.x;
        a.y += r1.y + r2.y + r3.y;
        a.z += r1.z + r2.z + r3.z;
        a.w += r1.w + r2.w + r3.w;
        *(float4*)&g_ctx_part[ts][b][ex * 4] = a;
    }
}

__global__ __launch_bounds__(512)
void k_ctx_reduce(float* __restrict__ ctx) {
    const int b = blockIdx.x;
    const int e = threadIdx.x;
    float s = 0.f;
#pragma unroll
    for (int k = 0; k < TS; k++) s += g_ctx_part[k][b][e];
    ctx[b * E + e] = s;
}

// ===========================================================================
extern "C" void kernel_launch(void* const* d_in, const int* in_sizes, int n_in,
                              void* d_out, int out_size) {
    const float* enc  = (const float*)d_in[0];
    const int*   lens = (const int*)  d_in[1];
    const float* ds   = (const float*)d_in[2];
    const float* Wenc = (const float*)d_in[4];
    const float* benc = (const float*)d_in[5];
    const float* Wdec = (const float*)d_in[6];
    const float* ww   = (const float*)d_in[7];
    const float* wb   = (const float*)d_in[8];

    float* ctx = (float*)d_out;           // [B,E]
    float* wgt = (float*)d_out + B * E;   // [B,T]

    k_wprep<<<dim3(E / 32, H / 32), dim3(32, 32)>>>(Wenc);   // idx 0
    k_dec<<<B, dim3(128, 8)>>>(ds, Wdec, benc);              // idx 1
    k_probe<<<1, 32>>>();                                    // idx 2
    k_erg<<<B * 16, 256>>>(enc, ww, wb);                     // idx 3 <- profiled
    k_softmax<<<B, 256>>>(lens, wgt);                        // idx 4
    k_ctx_part<<<dim3(B, TS), 512>>>(enc, wgt);              // idx 5
    k_ctx_reduce<<<B, E>>>(ctx);                             // idx 6
}